// round 2
// baseline (speedup 1.0000x reference)
#include <cuda_runtime.h>
#include <math.h>

#define D      128
#define TWO_D  256
#define MTILE  64
#define NTHREADS 256
#define KC     32

// Scratch for scatter-accumulated neighbor features: [2, 50000, 128] fp32 = 51.2MB
__device__ float g_neighbor[2 * 50000 * 128];

// ---- packed f32x2 helpers (sm_100+ PTX) -----------------------------------
#define PACK2(d, lo, hi) asm("mov.b64 %0, {%1, %2};" : "=l"(d) : "f"(lo), "f"(hi))
#define DUP2(d, v)       asm("mov.b64 %0, {%1, %1};" : "=l"(d) : "f"(v))
#define UNPACK2(lo, hi, s) asm("mov.b64 {%0, %1}, %2;" : "=f"(lo), "=f"(hi) : "l"(s))
#define FMA2(acc, a, b)  asm("fma.rn.f32x2 %0, %1, %2, %0;" : "+l"(acc) : "l"(a), "l"(b))

// ---------------------------------------------------------------------------
// Kernel 1: zero the neighbor accumulator
// ---------------------------------------------------------------------------
__global__ void zero_kernel(int n4) {
    int i = blockIdx.x * blockDim.x + threadIdx.x;
    if (i < n4) reinterpret_cast<float4*>(g_neighbor)[i] = make_float4(0.f, 0.f, 0.f, 0.f);
}

// ---------------------------------------------------------------------------
// Kernel 2: edge scatter-add. One warp per edge; lane owns one float4.
// ---------------------------------------------------------------------------
__global__ void scatter_kernel(const float* __restrict__ x,
                               const int* __restrict__ esrc,
                               const int* __restrict__ edst,
                               int E, int N) {
    int e    = (blockIdx.x * blockDim.x + threadIdx.x) >> 5;
    int lane = threadIdx.x & 31;
    if (e >= E) return;
    int s = esrc[e];
    int t = edst[e];
#pragma unroll
    for (int b = 0; b < 2; b++) {
        const float4 v = *reinterpret_cast<const float4*>(
            x + ((size_t)(b * N + s)) * D + lane * 4);
        float* p = g_neighbor + ((size_t)(b * N + t)) * D + lane * 4;
        asm volatile("red.global.add.v4.f32 [%0], {%1, %2, %3, %4};"
                     :: "l"(p), "f"(v.x), "f"(v.y), "f"(v.z), "f"(v.w)
                     : "memory");
    }
}

// ---------------------------------------------------------------------------
// Kernel 3: fused LN(x) ++ LN(neighbor/deg) -> GEMM1 -> GELU -> GEMM2 -> +x
// GEMM inner loops use packed fma.rn.f32x2 (2 MAC/lane/instr).
// ---------------------------------------------------------------------------
__device__ __forceinline__ int swz(int k) { return ((k >> 2) & 15) << 2; }

__global__ __launch_bounds__(NTHREADS, 2)
void fused_kernel(const float* __restrict__ x, const float* __restrict__ degree,
                  const float* __restrict__ sn_g, const float* __restrict__ sn_b,
                  const float* __restrict__ nn_g, const float* __restrict__ nn_b,
                  const float* __restrict__ W1, const float* __restrict__ b1,
                  const float* __restrict__ W2, const float* __restrict__ b2,
                  float* __restrict__ out, int N, int nrows) {
    extern __shared__ float sm[];
    float* sA = sm;                     // [256][64] swizzled (h0^T, later h1^T)
    float* wt = sm + TWO_D * MTILE;     // [32][256] weight chunk staging

    const int tid  = threadIdx.x;
    const int lane = tid & 31;
    const int warp = tid >> 5;
    const int row0 = blockIdx.x * MTILE;

    // ---------------- Stage 1: LayerNorms, write transposed into sA ----------
    {
        const float4 g1  = *reinterpret_cast<const float4*>(sn_g + lane * 4);
        const float4 be1 = *reinterpret_cast<const float4*>(sn_b + lane * 4);
        const float4 g2  = *reinterpret_cast<const float4*>(nn_g + lane * 4);
        const float4 be2 = *reinterpret_cast<const float4*>(nn_b + lane * 4);
#pragma unroll
        for (int rr = 0; rr < 8; rr++) {
            const int r    = warp * 8 + rr;   // 0..63
            const int grow = row0 + r;
            const int k0   = lane * 4;
            const int s0   = swz(k0);
            const int s1   = swz(k0 + 128);
            if (grow < nrows) {
                float4 xv = *reinterpret_cast<const float4*>(x + (size_t)grow * D + lane * 4);
                float sum  = xv.x + xv.y + xv.z + xv.w;
                float sumq = xv.x * xv.x + xv.y * xv.y + xv.z * xv.z + xv.w * xv.w;
#pragma unroll
                for (int o = 16; o > 0; o >>= 1) {
                    sum  += __shfl_xor_sync(0xffffffffu, sum, o);
                    sumq += __shfl_xor_sync(0xffffffffu, sumq, o);
                }
                float m    = sum * (1.0f / 128.0f);
                float rstd = rsqrtf(sumq * (1.0f / 128.0f) - m * m + 1e-5f);
                sA[(k0 + 0) * MTILE + (r ^ s0)] = (xv.x - m) * rstd * g1.x + be1.x;
                sA[(k0 + 1) * MTILE + (r ^ s0)] = (xv.y - m) * rstd * g1.y + be1.y;
                sA[(k0 + 2) * MTILE + (r ^ s0)] = (xv.z - m) * rstd * g1.z + be1.z;
                sA[(k0 + 3) * MTILE + (r ^ s0)] = (xv.w - m) * rstd * g1.w + be1.w;
                int   node = grow % N;
                float inv  = 1.0f / fmaxf(degree[node], 1.0f);
                float4 nv = *reinterpret_cast<const float4*>(
                    g_neighbor + (size_t)grow * D + lane * 4);
                nv.x *= inv; nv.y *= inv; nv.z *= inv; nv.w *= inv;
                sum  = nv.x + nv.y + nv.z + nv.w;
                sumq = nv.x * nv.x + nv.y * nv.y + nv.z * nv.z + nv.w * nv.w;
#pragma unroll
                for (int o = 16; o > 0; o >>= 1) {
                    sum  += __shfl_xor_sync(0xffffffffu, sum, o);
                    sumq += __shfl_xor_sync(0xffffffffu, sumq, o);
                }
                m    = sum * (1.0f / 128.0f);
                rstd = rsqrtf(sumq * (1.0f / 128.0f) - m * m + 1e-5f);
                sA[(k0 + 128) * MTILE + (r ^ s1)] = (nv.x - m) * rstd * g2.x + be2.x;
                sA[(k0 + 129) * MTILE + (r ^ s1)] = (nv.y - m) * rstd * g2.y + be2.y;
                sA[(k0 + 130) * MTILE + (r ^ s1)] = (nv.z - m) * rstd * g2.z + be2.z;
                sA[(k0 + 131) * MTILE + (r ^ s1)] = (nv.w - m) * rstd * g2.w + be2.w;
            } else {
#pragma unroll
                for (int j = 0; j < 4; j++) {
                    sA[(k0 + j)       * MTILE + (r ^ s0)] = 0.f;
                    sA[(k0 + 128 + j) * MTILE + (r ^ s1)] = 0.f;
                }
            }
        }
    }
    __syncthreads();

    // ---------------- Stage 2: GEMM1 (64x256x256), packed f32x2 --------------
    const int tm = tid & 7;     // rows tm*8 .. tm*8+7
    const int tn = tid >> 3;    // cols tn*8 .. tn*8+7
    unsigned long long cc[8][4];  // [i][jp], jp packs cols (2jp, 2jp+1)
#pragma unroll
    for (int i = 0; i < 8; i++)
#pragma unroll
        for (int j = 0; j < 4; j++) cc[i][j] = 0ull;

    for (int kc = 0; kc < TWO_D; kc += KC) {
        __syncthreads();
#pragma unroll
        for (int it = 0; it < (KC * TWO_D / 4) / NTHREADS; it++) {  // 8
            int idx = it * NTHREADS + tid;
            int kr  = idx >> 6;
            int nc  = (idx & 63) << 2;
            *reinterpret_cast<float4*>(wt + kr * TWO_D + nc) =
                *reinterpret_cast<const float4*>(W1 + (size_t)(kc + kr) * TWO_D + nc);
        }
        __syncthreads();
#pragma unroll 4
        for (int kk = 0; kk < KC; kk++) {
            const int k = kc + kk;
            const int s = swz(k);
            float4 a0  = *reinterpret_cast<const float4*>(sA + k * MTILE + ((tm * 8)     ^ s));
            float4 a1  = *reinterpret_cast<const float4*>(sA + k * MTILE + ((tm * 8 + 4) ^ s));
            float4 b0  = *reinterpret_cast<const float4*>(wt + kk * TWO_D + tn * 8);
            float4 b1v = *reinterpret_cast<const float4*>(wt + kk * TWO_D + tn * 8 + 4);
            float av[8] = {a0.x, a0.y, a0.z, a0.w, a1.x, a1.y, a1.z, a1.w};
            unsigned long long ad[8], bp[4];
#pragma unroll
            for (int i = 0; i < 8; i++) DUP2(ad[i], av[i]);
            PACK2(bp[0], b0.x,  b0.y);
            PACK2(bp[1], b0.z,  b0.w);
            PACK2(bp[2], b1v.x, b1v.y);
            PACK2(bp[3], b1v.z, b1v.w);
#pragma unroll
            for (int i = 0; i < 8; i++)
#pragma unroll
                for (int j = 0; j < 4; j++) FMA2(cc[i][j], ad[i], bp[j]);
        }
    }
    __syncthreads();

    // ---------------- Stage 3: bias + exact GELU, write h1^T into sA --------
    {
        float4 bb0 = *reinterpret_cast<const float4*>(b1 + tn * 8);
        float4 bb1 = *reinterpret_cast<const float4*>(b1 + tn * 8 + 4);
        float bvv[8] = {bb0.x, bb0.y, bb0.z, bb0.w, bb1.x, bb1.y, bb1.z, bb1.w};
#pragma unroll
        for (int jp = 0; jp < 4; jp++) {
            const int n0 = tn * 8 + 2 * jp;
            const int s0 = swz(n0);
            const int s1 = swz(n0 + 1);
#pragma unroll
            for (int i = 0; i < 8; i++) {
                float lo, hi;
                UNPACK2(lo, hi, cc[i][jp]);
                float v0 = lo + bvv[2 * jp];
                float v1 = hi + bvv[2 * jp + 1];
                v0 = 0.5f * v0 * (1.0f + erff(v0 * 0.70710678118654752f));
                v1 = 0.5f * v1 * (1.0f + erff(v1 * 0.70710678118654752f));
                sA[n0       * MTILE + ((tm * 8 + i) ^ s0)] = v0;
                sA[(n0 + 1) * MTILE + ((tm * 8 + i) ^ s1)] = v1;
            }
        }
    }
    __syncthreads();

    // ---------------- Stage 4: GEMM2 (64x128x256), packed f32x2 --------------
    const int tn2 = tid >> 3;   // cols tn2*4 .. tn2*4+3
    unsigned long long c2[8][2];
#pragma unroll
    for (int i = 0; i < 8; i++) { c2[i][0] = 0ull; c2[i][1] = 0ull; }

    for (int kc = 0; kc < TWO_D; kc += KC) {
        __syncthreads();
#pragma unroll
        for (int it = 0; it < (KC * D / 4) / NTHREADS; it++) {      // 4
            int idx = it * NTHREADS + tid;
            int kr  = idx >> 5;
            int nc  = (idx & 31) << 2;
            *reinterpret_cast<float4*>(wt + kr * D + nc) =
                *reinterpret_cast<const float4*>(W2 + (size_t)(kc + kr) * D + nc);
        }
        __syncthreads();
#pragma unroll 4
        for (int kk = 0; kk < KC; kk++) {
            const int k = kc + kk;
            const int s = swz(k);
            float4 a0 = *reinterpret_cast<const float4*>(sA + k * MTILE + ((tm * 8)     ^ s));
            float4 a1 = *reinterpret_cast<const float4*>(sA + k * MTILE + ((tm * 8 + 4) ^ s));
            float4 b0 = *reinterpret_cast<const float4*>(wt + kk * D + tn2 * 4);
            float av[8] = {a0.x, a0.y, a0.z, a0.w, a1.x, a1.y, a1.z, a1.w};
            unsigned long long ad[8], bp2[2];
#pragma unroll
            for (int i = 0; i < 8; i++) DUP2(ad[i], av[i]);
            PACK2(bp2[0], b0.x, b0.y);
            PACK2(bp2[1], b0.z, b0.w);
#pragma unroll
            for (int i = 0; i < 8; i++) {
                FMA2(c2[i][0], ad[i], bp2[0]);
                FMA2(c2[i][1], ad[i], bp2[1]);
            }
        }
    }

    // ---------------- Stage 5: bias + residual + store ----------------------
    {
        float4 bb = *reinterpret_cast<const float4*>(b2 + tn2 * 4);
#pragma unroll
        for (int i = 0; i < 8; i++) {
            int grow = row0 + tm * 8 + i;
            if (grow < nrows) {
                float c0, c1, c2v, c3;
                UNPACK2(c0, c1, c2[i][0]);
                UNPACK2(c2v, c3, c2[i][1]);
                float4 xv = *reinterpret_cast<const float4*>(x + (size_t)grow * D + tn2 * 4);
                float4 o;
                o.x = xv.x + c0  + bb.x;
                o.y = xv.y + c1  + bb.y;
                o.z = xv.z + c2v + bb.z;
                o.w = xv.w + c3  + bb.w;
                *reinterpret_cast<float4*>(out + (size_t)grow * D + tn2 * 4) = o;
            }
        }
    }
}

// ---------------------------------------------------------------------------
extern "C" void kernel_launch(void* const* d_in, const int* in_sizes, int n_in,
                              void* d_out, int out_size) {
    const float* x      = (const float*)d_in[0];
    const int*   esrc   = (const int*)  d_in[1];
    const int*   edst   = (const int*)  d_in[2];
    const float* degree = (const float*)d_in[3];
    const float* sn_g   = (const float*)d_in[4];
    const float* sn_b   = (const float*)d_in[5];
    const float* nn_g   = (const float*)d_in[6];
    const float* nn_b   = (const float*)d_in[7];
    const float* W1     = (const float*)d_in[8];
    const float* b1     = (const float*)d_in[9];
    const float* W2     = (const float*)d_in[10];
    const float* b2     = (const float*)d_in[11];

    const int E     = in_sizes[1];
    const int nrows = in_sizes[0] / D;   // B*N
    const int N     = in_sizes[3];       // degree length

    const int n4 = nrows * (D / 4);
    zero_kernel<<<(n4 + 255) / 256, 256>>>(n4);
    scatter_kernel<<<(E + 7) / 8, 256>>>(x, esrc, edst, E, N);

    const int smem = (TWO_D * MTILE + KC * TWO_D) * (int)sizeof(float); // 98304
    cudaFuncSetAttribute(fused_kernel, cudaFuncAttributeMaxDynamicSharedMemorySize, smem);
    fused_kernel<<<(nrows + MTILE - 1) / MTILE, NTHREADS, smem>>>(
        x, degree, sn_g, sn_b, nn_g, nn_b, W1, b1, W2, b2,
        (float*)d_out, N, nrows);
}

// round 3
// speedup vs baseline: 1.0785x; 1.0785x over previous
#include <cuda_runtime.h>
#include <math.h>

#define D      128
#define TWO_D  256
#define MTILE  64
#define NTHREADS 256
#define KC     32
#define MAXN   50000
#define MAXE   800000

// Scratch: gathered+normalized neighbor features [2, N, D] fp32 (51.2MB)
__device__ float g_neighbor[2 * MAXN * D];
// CSR structures
__device__ int g_base[MAXN + 1];
__device__ int g_cursor[MAXN];
__device__ int g_csr[MAXE];

// ---- packed f32x2 helpers (sm_100+ PTX) -----------------------------------
#define PACK2(d, lo, hi) asm("mov.b64 %0, {%1, %2};" : "=l"(d) : "f"(lo), "f"(hi))
#define DUP2(d, v)       asm("mov.b64 %0, {%1, %1};" : "=l"(d) : "f"(v))
#define UNPACK2(lo, hi, s) asm("mov.b64 {%0, %1}, %2;" : "=f"(lo), "=f"(hi) : "l"(s))
#define FMA2(acc, a, b)  asm("fma.rn.f32x2 %0, %1, %2, %0;" : "+l"(acc) : "l"(a), "l"(b))

// ---------------------------------------------------------------------------
// Kernel 1: single-block exclusive scan of (int)degree -> g_base; zero cursors.
// ---------------------------------------------------------------------------
__global__ void scan_kernel(const float* __restrict__ degree, int N) {
    __shared__ int warp_sums[32];
    __shared__ int s_carry;
    const int tid  = threadIdx.x;
    const int lane = tid & 31;
    const int wid  = tid >> 5;
    if (tid == 0) s_carry = 0;
    __syncthreads();

    for (int chunk = 0; chunk < N; chunk += 1024) {
        int i = chunk + tid;
        int v = (i < N) ? (int)degree[i] : 0;
        // inclusive scan within warp
        int inc = v;
#pragma unroll
        for (int o = 1; o < 32; o <<= 1) {
            int t = __shfl_up_sync(0xffffffffu, inc, o);
            if (lane >= o) inc += t;
        }
        if (lane == 31) warp_sums[wid] = inc;
        __syncthreads();
        if (wid == 0) {
            int ws = (lane < 32) ? warp_sums[lane] : 0;
#pragma unroll
            for (int o = 1; o < 32; o <<= 1) {
                int t = __shfl_up_sync(0xffffffffu, ws, o);
                if (lane >= o) ws += t;
            }
            warp_sums[lane] = ws;   // inclusive warp prefix
        }
        __syncthreads();
        int warp_prefix = (wid > 0) ? warp_sums[wid - 1] : 0;
        int excl = s_carry + warp_prefix + inc - v;
        if (i < N) {
            g_base[i]   = excl;
            g_cursor[i] = 0;
        }
        __syncthreads();
        if (tid == 1023) s_carry += warp_sums[31];
        __syncthreads();
    }
    if (tid == 0) g_base[N] = s_carry;
}

// ---------------------------------------------------------------------------
// Kernel 2: CSR fill — place each edge's src into its dst bucket.
// ---------------------------------------------------------------------------
__global__ void fill_kernel(const int* __restrict__ esrc,
                            const int* __restrict__ edst, int E) {
    int e = blockIdx.x * blockDim.x + threadIdx.x;
    if (e >= E) return;
    int t   = edst[e];
    int pos = g_base[t] + atomicAdd(&g_cursor[t], 1);
    if (pos < MAXE) g_csr[pos] = esrc[e];
}

// ---------------------------------------------------------------------------
// Kernel 3: gather — one warp per node, both batches; register accumulate,
// single store, pre-scaled by 1/clip(deg,1).
// ---------------------------------------------------------------------------
__global__ void gather_kernel(const float* __restrict__ x,
                              const float* __restrict__ degree, int N) {
    int n    = (blockIdx.x * blockDim.x + threadIdx.x) >> 5;
    int lane = threadIdx.x & 31;
    if (n >= N) return;
    int   deg = (int)degree[n];
    float inv = 1.0f / fmaxf(degree[n], 1.0f);
    int   b0  = g_base[n];

    float4 a0 = make_float4(0.f, 0.f, 0.f, 0.f);
    float4 a1 = make_float4(0.f, 0.f, 0.f, 0.f);

    int j = 0;
    for (; j + 2 <= deg; j += 2) {
        int s0 = g_csr[b0 + j];
        int s1 = g_csr[b0 + j + 1];
        const float4 v00 = *reinterpret_cast<const float4*>(x + (size_t)s0 * D + lane * 4);
        const float4 v01 = *reinterpret_cast<const float4*>(x + ((size_t)(N + s0)) * D + lane * 4);
        const float4 v10 = *reinterpret_cast<const float4*>(x + (size_t)s1 * D + lane * 4);
        const float4 v11 = *reinterpret_cast<const float4*>(x + ((size_t)(N + s1)) * D + lane * 4);
        a0.x += v00.x; a0.y += v00.y; a0.z += v00.z; a0.w += v00.w;
        a1.x += v01.x; a1.y += v01.y; a1.z += v01.z; a1.w += v01.w;
        a0.x += v10.x; a0.y += v10.y; a0.z += v10.z; a0.w += v10.w;
        a1.x += v11.x; a1.y += v11.y; a1.z += v11.z; a1.w += v11.w;
    }
    if (j < deg) {
        int s0 = g_csr[b0 + j];
        const float4 v00 = *reinterpret_cast<const float4*>(x + (size_t)s0 * D + lane * 4);
        const float4 v01 = *reinterpret_cast<const float4*>(x + ((size_t)(N + s0)) * D + lane * 4);
        a0.x += v00.x; a0.y += v00.y; a0.z += v00.z; a0.w += v00.w;
        a1.x += v01.x; a1.y += v01.y; a1.z += v01.z; a1.w += v01.w;
    }
    a0.x *= inv; a0.y *= inv; a0.z *= inv; a0.w *= inv;
    a1.x *= inv; a1.y *= inv; a1.z *= inv; a1.w *= inv;
    *reinterpret_cast<float4*>(g_neighbor + (size_t)n * D + lane * 4)       = a0;
    *reinterpret_cast<float4*>(g_neighbor + ((size_t)(N + n)) * D + lane * 4) = a1;
}

// ---------------------------------------------------------------------------
// Kernel 4: fused LN(x) ++ LN(neighbor) -> GEMM1 -> GELU -> GEMM2 -> +x
// ---------------------------------------------------------------------------
__device__ __forceinline__ int swz(int k) { return ((k >> 2) & 15) << 2; }

__global__ __launch_bounds__(NTHREADS, 2)
void fused_kernel(const float* __restrict__ x,
                  const float* __restrict__ sn_g, const float* __restrict__ sn_b,
                  const float* __restrict__ nn_g, const float* __restrict__ nn_b,
                  const float* __restrict__ W1, const float* __restrict__ b1,
                  const float* __restrict__ W2, const float* __restrict__ b2,
                  float* __restrict__ out, int nrows) {
    extern __shared__ float sm[];
    float* sA = sm;                     // [256][64] swizzled (h0^T, later h1^T)
    float* wt = sm + TWO_D * MTILE;     // [32][256] weight chunk staging

    const int tid  = threadIdx.x;
    const int lane = tid & 31;
    const int warp = tid >> 5;
    const int row0 = blockIdx.x * MTILE;

    // ---------------- Stage 1: LayerNorms, write transposed into sA ----------
    {
        const float4 g1  = *reinterpret_cast<const float4*>(sn_g + lane * 4);
        const float4 be1 = *reinterpret_cast<const float4*>(sn_b + lane * 4);
        const float4 g2  = *reinterpret_cast<const float4*>(nn_g + lane * 4);
        const float4 be2 = *reinterpret_cast<const float4*>(nn_b + lane * 4);
#pragma unroll
        for (int rr = 0; rr < 8; rr++) {
            const int r    = warp * 8 + rr;
            const int grow = row0 + r;
            const int k0   = lane * 4;
            const int s0   = swz(k0);
            const int s1   = swz(k0 + 128);
            if (grow < nrows) {
                float4 xv = *reinterpret_cast<const float4*>(x + (size_t)grow * D + lane * 4);
                float sum  = xv.x + xv.y + xv.z + xv.w;
                float sumq = xv.x * xv.x + xv.y * xv.y + xv.z * xv.z + xv.w * xv.w;
#pragma unroll
                for (int o = 16; o > 0; o >>= 1) {
                    sum  += __shfl_xor_sync(0xffffffffu, sum, o);
                    sumq += __shfl_xor_sync(0xffffffffu, sumq, o);
                }
                float m    = sum * (1.0f / 128.0f);
                float rstd = rsqrtf(sumq * (1.0f / 128.0f) - m * m + 1e-5f);
                sA[(k0 + 0) * MTILE + (r ^ s0)] = (xv.x - m) * rstd * g1.x + be1.x;
                sA[(k0 + 1) * MTILE + (r ^ s0)] = (xv.y - m) * rstd * g1.y + be1.y;
                sA[(k0 + 2) * MTILE + (r ^ s0)] = (xv.z - m) * rstd * g1.z + be1.z;
                sA[(k0 + 3) * MTILE + (r ^ s0)] = (xv.w - m) * rstd * g1.w + be1.w;
                float4 nv = *reinterpret_cast<const float4*>(
                    g_neighbor + (size_t)grow * D + lane * 4);
                sum  = nv.x + nv.y + nv.z + nv.w;
                sumq = nv.x * nv.x + nv.y * nv.y + nv.z * nv.z + nv.w * nv.w;
#pragma unroll
                for (int o = 16; o > 0; o >>= 1) {
                    sum  += __shfl_xor_sync(0xffffffffu, sum, o);
                    sumq += __shfl_xor_sync(0xffffffffu, sumq, o);
                }
                m    = sum * (1.0f / 128.0f);
                rstd = rsqrtf(sumq * (1.0f / 128.0f) - m * m + 1e-5f);
                sA[(k0 + 128) * MTILE + (r ^ s1)] = (nv.x - m) * rstd * g2.x + be2.x;
                sA[(k0 + 129) * MTILE + (r ^ s1)] = (nv.y - m) * rstd * g2.y + be2.y;
                sA[(k0 + 130) * MTILE + (r ^ s1)] = (nv.z - m) * rstd * g2.z + be2.z;
                sA[(k0 + 131) * MTILE + (r ^ s1)] = (nv.w - m) * rstd * g2.w + be2.w;
            } else {
#pragma unroll
                for (int jj = 0; jj < 4; jj++) {
                    sA[(k0 + jj)       * MTILE + (r ^ s0)] = 0.f;
                    sA[(k0 + 128 + jj) * MTILE + (r ^ s1)] = 0.f;
                }
            }
        }
    }
    __syncthreads();

    // ---------------- Stage 2: GEMM1 (64x256x256), packed f32x2 --------------
    const int tm = tid & 7;
    const int tn = tid >> 3;
    unsigned long long cc[8][4];
#pragma unroll
    for (int i = 0; i < 8; i++)
#pragma unroll
        for (int jj = 0; jj < 4; jj++) cc[i][jj] = 0ull;

    for (int kc = 0; kc < TWO_D; kc += KC) {
        __syncthreads();
#pragma unroll
        for (int it = 0; it < (KC * TWO_D / 4) / NTHREADS; it++) {
            int idx = it * NTHREADS + tid;
            int kr  = idx >> 6;
            int nc  = (idx & 63) << 2;
            *reinterpret_cast<float4*>(wt + kr * TWO_D + nc) =
                *reinterpret_cast<const float4*>(W1 + (size_t)(kc + kr) * TWO_D + nc);
        }
        __syncthreads();
#pragma unroll 4
        for (int kk = 0; kk < KC; kk++) {
            const int k = kc + kk;
            const int s = swz(k);
            float4 a0  = *reinterpret_cast<const float4*>(sA + k * MTILE + ((tm * 8)     ^ s));
            float4 a1  = *reinterpret_cast<const float4*>(sA + k * MTILE + ((tm * 8 + 4) ^ s));
            float4 b0  = *reinterpret_cast<const float4*>(wt + kk * TWO_D + tn * 8);
            float4 b1v = *reinterpret_cast<const float4*>(wt + kk * TWO_D + tn * 8 + 4);
            float av[8] = {a0.x, a0.y, a0.z, a0.w, a1.x, a1.y, a1.z, a1.w};
            unsigned long long ad[8], bp[4];
#pragma unroll
            for (int i = 0; i < 8; i++) DUP2(ad[i], av[i]);
            PACK2(bp[0], b0.x,  b0.y);
            PACK2(bp[1], b0.z,  b0.w);
            PACK2(bp[2], b1v.x, b1v.y);
            PACK2(bp[3], b1v.z, b1v.w);
#pragma unroll
            for (int i = 0; i < 8; i++)
#pragma unroll
                for (int jj = 0; jj < 4; jj++) FMA2(cc[i][jj], ad[i], bp[jj]);
        }
    }
    __syncthreads();

    // ---------------- Stage 3: bias + exact GELU, write h1^T into sA --------
    {
        float4 bb0 = *reinterpret_cast<const float4*>(b1 + tn * 8);
        float4 bb1 = *reinterpret_cast<const float4*>(b1 + tn * 8 + 4);
        float bvv[8] = {bb0.x, bb0.y, bb0.z, bb0.w, bb1.x, bb1.y, bb1.z, bb1.w};
#pragma unroll
        for (int jp = 0; jp < 4; jp++) {
            const int n0 = tn * 8 + 2 * jp;
            const int s0 = swz(n0);
            const int s1 = swz(n0 + 1);
#pragma unroll
            for (int i = 0; i < 8; i++) {
                float lo, hi;
                UNPACK2(lo, hi, cc[i][jp]);
                float v0 = lo + bvv[2 * jp];
                float v1 = hi + bvv[2 * jp + 1];
                v0 = 0.5f * v0 * (1.0f + erff(v0 * 0.70710678118654752f));
                v1 = 0.5f * v1 * (1.0f + erff(v1 * 0.70710678118654752f));
                sA[n0       * MTILE + ((tm * 8 + i) ^ s0)] = v0;
                sA[(n0 + 1) * MTILE + ((tm * 8 + i) ^ s1)] = v1;
            }
        }
    }
    __syncthreads();

    // ---------------- Stage 4: GEMM2 (64x128x256), packed f32x2 --------------
    const int tn2 = tid >> 3;
    unsigned long long c2[8][2];
#pragma unroll
    for (int i = 0; i < 8; i++) { c2[i][0] = 0ull; c2[i][1] = 0ull; }

    for (int kc = 0; kc < TWO_D; kc += KC) {
        __syncthreads();
#pragma unroll
        for (int it = 0; it < (KC * D / 4) / NTHREADS; it++) {
            int idx = it * NTHREADS + tid;
            int kr  = idx >> 5;
            int nc  = (idx & 31) << 2;
            *reinterpret_cast<float4*>(wt + kr * D + nc) =
                *reinterpret_cast<const float4*>(W2 + (size_t)(kc + kr) * D + nc);
        }
        __syncthreads();
#pragma unroll 4
        for (int kk = 0; kk < KC; kk++) {
            const int k = kc + kk;
            const int s = swz(k);
            float4 a0 = *reinterpret_cast<const float4*>(sA + k * MTILE + ((tm * 8)     ^ s));
            float4 a1 = *reinterpret_cast<const float4*>(sA + k * MTILE + ((tm * 8 + 4) ^ s));
            float4 b0 = *reinterpret_cast<const float4*>(wt + kk * D + tn2 * 4);
            float av[8] = {a0.x, a0.y, a0.z, a0.w, a1.x, a1.y, a1.z, a1.w};
            unsigned long long ad[8], bp2[2];
#pragma unroll
            for (int i = 0; i < 8; i++) DUP2(ad[i], av[i]);
            PACK2(bp2[0], b0.x, b0.y);
            PACK2(bp2[1], b0.z, b0.w);
#pragma unroll
            for (int i = 0; i < 8; i++) {
                FMA2(c2[i][0], ad[i], bp2[0]);
                FMA2(c2[i][1], ad[i], bp2[1]);
            }
        }
    }

    // ---------------- Stage 5: bias + residual + store ----------------------
    {
        float4 bb = *reinterpret_cast<const float4*>(b2 + tn2 * 4);
#pragma unroll
        for (int i = 0; i < 8; i++) {
            int grow = row0 + tm * 8 + i;
            if (grow < nrows) {
                float c0, c1, c2v, c3;
                UNPACK2(c0, c1, c2[i][0]);
                UNPACK2(c2v, c3, c2[i][1]);
                float4 xv = *reinterpret_cast<const float4*>(x + (size_t)grow * D + tn2 * 4);
                float4 o;
                o.x = xv.x + c0  + bb.x;
                o.y = xv.y + c1  + bb.y;
                o.z = xv.z + c2v + bb.z;
                o.w = xv.w + c3  + bb.w;
                *reinterpret_cast<float4*>(out + (size_t)grow * D + tn2 * 4) = o;
            }
        }
    }
}

// ---------------------------------------------------------------------------
extern "C" void kernel_launch(void* const* d_in, const int* in_sizes, int n_in,
                              void* d_out, int out_size) {
    const float* x      = (const float*)d_in[0];
    const int*   esrc   = (const int*)  d_in[1];
    const int*   edst   = (const int*)  d_in[2];
    const float* degree = (const float*)d_in[3];
    const float* sn_g   = (const float*)d_in[4];
    const float* sn_b   = (const float*)d_in[5];
    const float* nn_g   = (const float*)d_in[6];
    const float* nn_b   = (const float*)d_in[7];
    const float* W1     = (const float*)d_in[8];
    const float* b1     = (const float*)d_in[9];
    const float* W2     = (const float*)d_in[10];
    const float* b2     = (const float*)d_in[11];

    const int E     = in_sizes[1];
    const int nrows = in_sizes[0] / D;   // B*N
    const int N     = in_sizes[3];

    scan_kernel<<<1, 1024>>>(degree, N);
    fill_kernel<<<(E + 255) / 256, 256>>>(esrc, edst, E);
    gather_kernel<<<(N * 32 + 255) / 256, 256>>>(x, degree, N);

    const int smem = (TWO_D * MTILE + KC * TWO_D) * (int)sizeof(float); // 96KB
    cudaFuncSetAttribute(fused_kernel, cudaFuncAttributeMaxDynamicSharedMemorySize, smem);
    fused_kernel<<<(nrows + MTILE - 1) / MTILE, NTHREADS, smem>>>(
        x, sn_g, sn_b, nn_g, nn_b, W1, b1, W2, b2,
        (float*)d_out, nrows);
}

// round 6
// speedup vs baseline: 1.4633x; 1.3568x over previous
#include <cuda_runtime.h>
#include <cuda_bf16.h>
#include <cstdint>
#include <stdint.h>
#include <math.h>

#define D      128
#define TWO_D  256
#define MTILE  64
#define NTHREADS 256
#define MAXN   50000
#define MAXE   800000

// A image: 64 rows x 256 bf16, row stride 528 bytes (padded; conflict-free LDSM)
#define A_STRIDE 528
#define A_IMG    (64 * A_STRIDE)      // 33792
// B chunk rows: 80 bytes (32 bf16 + 16B pad)
#define SMEM_AHI 0
#define SMEM_ALO A_IMG
#define SMEM_BHI (2 * A_IMG)          // 67584
#define SMEM_BLO (SMEM_BHI + 20480)   // 88064
#define SMEM_TOTAL (SMEM_BLO + 20480) // 108544

// ---------------------------------------------------------------------------
// Device globals
// ---------------------------------------------------------------------------
__device__ float g_neighbor[2 * MAXN * D];
__device__ int   g_base[MAXN + 1];
__device__ int   g_cursor[MAXN];
__device__ int   g_csr[MAXE];
// W1^T split images: [8 kchunks][256 n][80 B]  = 163840 B per term
__device__ uint4 g_B1hi[10240];
__device__ uint4 g_B1lo[10240];
// W2^T split images: [8 kchunks][128 n][80 B]  = 81920 B per term
__device__ uint4 g_B2hi[5120];
__device__ uint4 g_B2lo[5120];

// ---------------------------------------------------------------------------
// helpers
// ---------------------------------------------------------------------------
__device__ __forceinline__ uint32_t smem_u32(const void* p) {
    uint32_t a;
    asm("{ .reg .u64 t; cvta.to.shared.u64 t, %1; cvt.u32.u64 %0, t; }" : "=r"(a) : "l"(p));
    return a;
}
__device__ __forceinline__ void ldsm4(uint32_t* r, uint32_t addr) {
    asm volatile("ldmatrix.sync.aligned.m8n8.x4.shared.b16 {%0,%1,%2,%3}, [%4];"
                 : "=r"(r[0]), "=r"(r[1]), "=r"(r[2]), "=r"(r[3]) : "r"(addr));
}
__device__ __forceinline__ void mma16816(float* d, const uint32_t* a, const uint32_t* b) {
    asm volatile("mma.sync.aligned.m16n8k16.row.col.f32.bf16.bf16.f32 "
                 "{%0,%1,%2,%3}, {%4,%5,%6,%7}, {%8,%9}, {%0,%1,%2,%3};"
                 : "+f"(d[0]), "+f"(d[1]), "+f"(d[2]), "+f"(d[3])
                 : "r"(a[0]), "r"(a[1]), "r"(a[2]), "r"(a[3]), "r"(b[0]), "r"(b[1]));
}
// A-image byte offset (row-major, k contiguous within 16B segs)
__device__ __forceinline__ int a_off(int row, int k) {
    return row * A_STRIDE + ((k >> 3) << 4) + ((k & 7) << 1);
}
// B chunk-image byte offset (chunk_bytes = n_rows * 80)
__device__ __forceinline__ int b_off(int n, int k, int chunk_bytes) {
    return (k >> 5) * chunk_bytes + n * 80 + (((k & 31) >> 3) << 4) + ((k & 7) << 1);
}
__device__ __forceinline__ void split_pair(char* hi_base, char* lo_base, int off,
                                           float v0, float v1) {
    __nv_bfloat16 h0 = __float2bfloat16(v0);
    __nv_bfloat16 h1 = __float2bfloat16(v1);
    __nv_bfloat16 l0 = __float2bfloat16(v0 - __bfloat162float(h0));
    __nv_bfloat16 l1 = __float2bfloat16(v1 - __bfloat162float(h1));
    *reinterpret_cast<__nv_bfloat162*>(hi_base + off) = __halves2bfloat162(h0, h1);
    *reinterpret_cast<__nv_bfloat162*>(lo_base + off) = __halves2bfloat162(l0, l1);
}

// ---------------------------------------------------------------------------
// Prep: transpose + split weights into chunked images
// ---------------------------------------------------------------------------
__global__ void prep_w1(const float* __restrict__ W1) {
    int idx = blockIdx.x * blockDim.x + threadIdx.x;   // n*128 + kpair
    if (idx >= 256 * 128) return;
    int n = idx >> 7, k = (idx & 127) << 1;
    float w0 = W1[(size_t)k * 256 + n];
    float w1 = W1[(size_t)(k + 1) * 256 + n];
    split_pair((char*)g_B1hi, (char*)g_B1lo, b_off(n, k, 20480), w0, w1);
}
__global__ void prep_w2(const float* __restrict__ W2) {
    int idx = blockIdx.x * blockDim.x + threadIdx.x;   // n*128 + kpair
    if (idx >= 128 * 128) return;
    int n = idx >> 7, k = (idx & 127) << 1;
    float w0 = W2[(size_t)k * 128 + n];
    float w1 = W2[(size_t)(k + 1) * 128 + n];
    split_pair((char*)g_B2hi, (char*)g_B2lo, b_off(n, k, 10240), w0, w1);
}

// ---------------------------------------------------------------------------
// CSR build + gather (unchanged, proven)
// ---------------------------------------------------------------------------
__global__ void scan_kernel(const float* __restrict__ degree, int N) {
    __shared__ int warp_sums[32];
    __shared__ int s_carry;
    const int tid = threadIdx.x, lane = tid & 31, wid = tid >> 5;
    if (tid == 0) s_carry = 0;
    __syncthreads();
    for (int chunk = 0; chunk < N; chunk += 1024) {
        int i = chunk + tid;
        int v = (i < N) ? (int)degree[i] : 0;
        int inc = v;
#pragma unroll
        for (int o = 1; o < 32; o <<= 1) {
            int t = __shfl_up_sync(0xffffffffu, inc, o);
            if (lane >= o) inc += t;
        }
        if (lane == 31) warp_sums[wid] = inc;
        __syncthreads();
        if (wid == 0) {
            int ws = warp_sums[lane];
#pragma unroll
            for (int o = 1; o < 32; o <<= 1) {
                int t = __shfl_up_sync(0xffffffffu, ws, o);
                if (lane >= o) ws += t;
            }
            warp_sums[lane] = ws;
        }
        __syncthreads();
        int warp_prefix = (wid > 0) ? warp_sums[wid - 1] : 0;
        int excl = s_carry + warp_prefix + inc - v;
        if (i < N) { g_base[i] = excl; g_cursor[i] = 0; }
        __syncthreads();
        if (tid == 1023) s_carry += warp_sums[31];
        __syncthreads();
    }
    if (tid == 0) g_base[N] = s_carry;
}

__global__ void fill_kernel(const int* __restrict__ esrc,
                            const int* __restrict__ edst, int E) {
    int e = blockIdx.x * blockDim.x + threadIdx.x;
    if (e >= E) return;
    int t = edst[e];
    int pos = g_base[t] + atomicAdd(&g_cursor[t], 1);
    if (pos < MAXE) g_csr[pos] = esrc[e];
}

__global__ void gather_kernel(const float* __restrict__ x,
                              const float* __restrict__ degree, int N) {
    int n = (blockIdx.x * blockDim.x + threadIdx.x) >> 5;
    int lane = threadIdx.x & 31;
    if (n >= N) return;
    int   deg = (int)degree[n];
    float inv = 1.0f / fmaxf(degree[n], 1.0f);
    int   b0  = g_base[n];
    float4 a0 = make_float4(0.f, 0.f, 0.f, 0.f);
    float4 a1 = make_float4(0.f, 0.f, 0.f, 0.f);
    int j = 0;
    for (; j + 2 <= deg; j += 2) {
        int s0 = g_csr[b0 + j], s1 = g_csr[b0 + j + 1];
        const float4 v00 = *reinterpret_cast<const float4*>(x + (size_t)s0 * D + lane * 4);
        const float4 v01 = *reinterpret_cast<const float4*>(x + ((size_t)(N + s0)) * D + lane * 4);
        const float4 v10 = *reinterpret_cast<const float4*>(x + (size_t)s1 * D + lane * 4);
        const float4 v11 = *reinterpret_cast<const float4*>(x + ((size_t)(N + s1)) * D + lane * 4);
        a0.x += v00.x + v10.x; a0.y += v00.y + v10.y;
        a0.z += v00.z + v10.z; a0.w += v00.w + v10.w;
        a1.x += v01.x + v11.x; a1.y += v01.y + v11.y;
        a1.z += v01.z + v11.z; a1.w += v01.w + v11.w;
    }
    if (j < deg) {
        int s0 = g_csr[b0 + j];
        const float4 v00 = *reinterpret_cast<const float4*>(x + (size_t)s0 * D + lane * 4);
        const float4 v01 = *reinterpret_cast<const float4*>(x + ((size_t)(N + s0)) * D + lane * 4);
        a0.x += v00.x; a0.y += v00.y; a0.z += v00.z; a0.w += v00.w;
        a1.x += v01.x; a1.y += v01.y; a1.z += v01.z; a1.w += v01.w;
    }
    a0.x *= inv; a0.y *= inv; a0.z *= inv; a0.w *= inv;
    a1.x *= inv; a1.y *= inv; a1.z *= inv; a1.w *= inv;
    *reinterpret_cast<float4*>(g_neighbor + (size_t)n * D + lane * 4)         = a0;
    *reinterpret_cast<float4*>(g_neighbor + ((size_t)(N + n)) * D + lane * 4) = a1;
}

// ---------------------------------------------------------------------------
// Fused kernel: LN -> split-bf16 mma.sync GEMM1 -> GELU -> GEMM2 -> +x
// 64 rows/CTA, 8 warps: wm = warp&1 (2 in M), wn = warp>>1 (4 in N)
// ---------------------------------------------------------------------------
__global__ void __launch_bounds__(NTHREADS, 1)
fused_kernel(const float* __restrict__ x,
             const float* __restrict__ sn_g, const float* __restrict__ sn_b,
             const float* __restrict__ nn_g, const float* __restrict__ nn_b,
             const float* __restrict__ b1,  const float* __restrict__ b2,
             float* __restrict__ out, int nrows) {
    extern __shared__ char sm[];
    const uint32_t smem_base = smem_u32(sm);
    char* Ahi = sm + SMEM_AHI;
    char* Alo = sm + SMEM_ALO;

    const int tid  = threadIdx.x;
    const int lane = tid & 31;
    const int warp = tid >> 5;
    const int wm   = warp & 1;
    const int wn   = warp >> 1;
    const int row0 = blockIdx.x * MTILE;
    const int g    = lane >> 3;     // ldmatrix tile group
    const int lr   = lane & 7;

    // ---------------- Stage 1: LayerNorms -> A_hi/A_lo images ---------------
    {
        const float4 g1  = *reinterpret_cast<const float4*>(sn_g + lane * 4);
        const float4 be1 = *reinterpret_cast<const float4*>(sn_b + lane * 4);
        const float4 g2  = *reinterpret_cast<const float4*>(nn_g + lane * 4);
        const float4 be2 = *reinterpret_cast<const float4*>(nn_b + lane * 4);
        const int k0 = lane * 4;
#pragma unroll
        for (int rr = 0; rr < 8; rr++) {
            const int r    = warp * 8 + rr;
            const int grow = row0 + r;
            if (grow < nrows) {
                float4 xv = *reinterpret_cast<const float4*>(x + (size_t)grow * D + k0);
                float sum  = xv.x + xv.y + xv.z + xv.w;
                float sumq = xv.x * xv.x + xv.y * xv.y + xv.z * xv.z + xv.w * xv.w;
#pragma unroll
                for (int o = 16; o > 0; o >>= 1) {
                    sum  += __shfl_xor_sync(0xffffffffu, sum, o);
                    sumq += __shfl_xor_sync(0xffffffffu, sumq, o);
                }
                float mn   = sum * (1.0f / 128.0f);
                float rstd = rsqrtf(sumq * (1.0f / 128.0f) - mn * mn + 1e-5f);
                split_pair(Ahi, Alo, a_off(r, k0),     (xv.x - mn) * rstd * g1.x + be1.x,
                                                       (xv.y - mn) * rstd * g1.y + be1.y);
                split_pair(Ahi, Alo, a_off(r, k0 + 2), (xv.z - mn) * rstd * g1.z + be1.z,
                                                       (xv.w - mn) * rstd * g1.w + be1.w);
                float4 nv = *reinterpret_cast<const float4*>(g_neighbor + (size_t)grow * D + k0);
                sum  = nv.x + nv.y + nv.z + nv.w;
                sumq = nv.x * nv.x + nv.y * nv.y + nv.z * nv.z + nv.w * nv.w;
#pragma unroll
                for (int o = 16; o > 0; o >>= 1) {
                    sum  += __shfl_xor_sync(0xffffffffu, sum, o);
                    sumq += __shfl_xor_sync(0xffffffffu, sumq, o);
                }
                mn   = sum * (1.0f / 128.0f);
                rstd = rsqrtf(sumq * (1.0f / 128.0f) - mn * mn + 1e-5f);
                split_pair(Ahi, Alo, a_off(r, 128 + k0),     (nv.x - mn) * rstd * g2.x + be2.x,
                                                             (nv.y - mn) * rstd * g2.y + be2.y);
                split_pair(Ahi, Alo, a_off(r, 128 + k0 + 2), (nv.z - mn) * rstd * g2.z + be2.z,
                                                             (nv.w - mn) * rstd * g2.w + be2.w);
            } else {
                split_pair(Ahi, Alo, a_off(r, k0),           0.f, 0.f);
                split_pair(Ahi, Alo, a_off(r, k0 + 2),       0.f, 0.f);
                split_pair(Ahi, Alo, a_off(r, 128 + k0),     0.f, 0.f);
                split_pair(Ahi, Alo, a_off(r, 128 + k0 + 2), 0.f, 0.f);
            }
        }
    }

    // ---------------- Stage 2: GEMM1 (64 x 256 x 256, 3 split terms) --------
    float acc[2][8][4];
#pragma unroll
    for (int i = 0; i < 2; i++)
#pragma unroll
        for (int j = 0; j < 8; j++)
#pragma unroll
            for (int r = 0; r < 4; r++) acc[i][j][r] = 0.f;

    for (int kc = 0; kc < 8; kc++) {
        __syncthreads();
        {
            uint4* dhi = reinterpret_cast<uint4*>(sm + SMEM_BHI);
            uint4* dlo = reinterpret_cast<uint4*>(sm + SMEM_BLO);
#pragma unroll
            for (int it = 0; it < 5; it++) {
                int i = it * NTHREADS + tid;
                dhi[i] = g_B1hi[kc * 1280 + i];
                dlo[i] = g_B1lo[kc * 1280 + i];
            }
        }
        __syncthreads();
#pragma unroll
        for (int ks = 0; ks < 2; ks++) {
            const int kabs = kc * 32 + ks * 16;
            uint32_t ahi[2][4], alo[2][4];
#pragma unroll
            for (int ti = 0; ti < 2; ti++) {
                int row = wm * 32 + ti * 16 + (g & 1) * 8 + lr;
                uint32_t off = row * A_STRIDE + (((kabs >> 3) + (g >> 1)) << 4);
                ldsm4(ahi[ti], smem_base + SMEM_AHI + off);
                ldsm4(alo[ti], smem_base + SMEM_ALO + off);
            }
#pragma unroll
            for (int jj = 0; jj < 4; jj++) {
                int n = wn * 64 + jj * 16 + (g >> 1) * 8 + lr;
                uint32_t boff = n * 80 + (((ks * 16 >> 3) + (g & 1)) << 4);
                uint32_t bhi[4], blo[4];
                ldsm4(bhi, smem_base + SMEM_BHI + boff);
                ldsm4(blo, smem_base + SMEM_BLO + boff);
#pragma unroll
                for (int ti = 0; ti < 2; ti++) {
                    mma16816(acc[ti][2 * jj],     ahi[ti], bhi);
                    mma16816(acc[ti][2 * jj],     ahi[ti], blo);
                    mma16816(acc[ti][2 * jj],     alo[ti], bhi);
                    mma16816(acc[ti][2 * jj + 1], ahi[ti], bhi + 2);
                    mma16816(acc[ti][2 * jj + 1], ahi[ti], blo + 2);
                    mma16816(acc[ti][2 * jj + 1], alo[ti], bhi + 2);
                }
            }
        }
    }

    // ---------------- Stage 3: bias + GELU -> A2 images (reuse A bufs) ------
    __syncthreads();
#pragma unroll
    for (int tj = 0; tj < 8; tj++) {
        const int col = wn * 64 + tj * 8 + (lane & 3) * 2;
        const float2 bb = *reinterpret_cast<const float2*>(b1 + col);
#pragma unroll
        for (int ti = 0; ti < 2; ti++)
#pragma unroll
            for (int rp = 0; rp < 2; rp++) {
                int row = wm * 32 + ti * 16 + (lane >> 2) + rp * 8;
                float v0 = acc[ti][tj][rp * 2 + 0] + bb.x;
                float v1 = acc[ti][tj][rp * 2 + 1] + bb.y;
                v0 = 0.5f * v0 * (1.0f + erff(v0 * 0.70710678118654752f));
                v1 = 0.5f * v1 * (1.0f + erff(v1 * 0.70710678118654752f));
                split_pair(Ahi, Alo, a_off(row, col), v0, v1);
            }
    }

    // ---------------- Stage 4: GEMM2 (64 x 128 x 256, 3 split terms) --------
    float c2[2][4][4];
#pragma unroll
    for (int i = 0; i < 2; i++)
#pragma unroll
        for (int j = 0; j < 4; j++)
#pragma unroll
            for (int r = 0; r < 4; r++) c2[i][j][r] = 0.f;

    for (int kc = 0; kc < 8; kc++) {
        __syncthreads();
        {
            uint4* dhi = reinterpret_cast<uint4*>(sm + SMEM_BHI);
            uint4* dlo = reinterpret_cast<uint4*>(sm + SMEM_BLO);
            for (int i = tid; i < 640; i += NTHREADS) {
                dhi[i] = g_B2hi[kc * 640 + i];
                dlo[i] = g_B2lo[kc * 640 + i];
            }
        }
        __syncthreads();
#pragma unroll
        for (int ks = 0; ks < 2; ks++) {
            const int kabs = kc * 32 + ks * 16;
            uint32_t ahi[2][4], alo[2][4];
#pragma unroll
            for (int ti = 0; ti < 2; ti++) {
                int row = wm * 32 + ti * 16 + (g & 1) * 8 + lr;
                uint32_t off = row * A_STRIDE + (((kabs >> 3) + (g >> 1)) << 4);
                ldsm4(ahi[ti], smem_base + SMEM_AHI + off);
                ldsm4(alo[ti], smem_base + SMEM_ALO + off);
            }
#pragma unroll
            for (int jj = 0; jj < 2; jj++) {
                int n = wn * 32 + jj * 16 + (g >> 1) * 8 + lr;
                uint32_t boff = n * 80 + (((ks * 16 >> 3) + (g & 1)) << 4);
                uint32_t bhi[4], blo[4];
                ldsm4(bhi, smem_base + SMEM_BHI + boff);
                ldsm4(blo, smem_base + SMEM_BLO + boff);
#pragma unroll
                for (int ti = 0; ti < 2; ti++) {
                    mma16816(c2[ti][2 * jj],     ahi[ti], bhi);
                    mma16816(c2[ti][2 * jj],     ahi[ti], blo);
                    mma16816(c2[ti][2 * jj],     alo[ti], bhi);
                    mma16816(c2[ti][2 * jj + 1], ahi[ti], bhi + 2);
                    mma16816(c2[ti][2 * jj + 1], ahi[ti], blo + 2);
                    mma16816(c2[ti][2 * jj + 1], alo[ti], bhi + 2);
                }
            }
        }
    }

    // ---------------- Stage 5: bias + residual + store ----------------------
#pragma unroll
    for (int tj = 0; tj < 4; tj++) {
        const int col = wn * 32 + tj * 8 + (lane & 3) * 2;
        const float2 bb = *reinterpret_cast<const float2*>(b2 + col);
#pragma unroll
        for (int ti = 0; ti < 2; ti++)
#pragma unroll
            for (int rp = 0; rp < 2; rp++) {
                int row  = wm * 32 + ti * 16 + (lane >> 2) + rp * 8;
                int grow = row0 + row;
                if (grow < nrows) {
                    const float2 xv = *reinterpret_cast<const float2*>(x + (size_t)grow * D + col);
                    float2 o;
                    o.x = xv.x + c2[ti][tj][rp * 2 + 0] + bb.x;
                    o.y = xv.y + c2[ti][tj][rp * 2 + 1] + bb.y;
                    *reinterpret_cast<float2*>(out + (size_t)grow * D + col) = o;
                }
            }
    }
}

// ---------------------------------------------------------------------------
extern "C" void kernel_launch(void* const* d_in, const int* in_sizes, int n_in,
                              void* d_out, int out_size) {
    const float* x      = (const float*)d_in[0];
    const int*   esrc   = (const int*)  d_in[1];
    const int*   edst   = (const int*)  d_in[2];
    const float* degree = (const float*)d_in[3];
    const float* sn_g   = (const float*)d_in[4];
    const float* sn_b   = (const float*)d_in[5];
    const float* nn_g   = (const float*)d_in[6];
    const float* nn_b   = (const float*)d_in[7];
    const float* W1     = (const float*)d_in[8];
    const float* b1     = (const float*)d_in[9];
    const float* W2     = (const float*)d_in[10];
    const float* b2     = (const float*)d_in[11];

    const int E     = in_sizes[1];
    const int nrows = in_sizes[0] / D;   // B*N
    const int N     = in_sizes[3];

    prep_w1<<<(256 * 128 + 255) / 256, 256>>>(W1);
    prep_w2<<<(128 * 128 + 255) / 256, 256>>>(W2);
    scan_kernel<<<1, 1024>>>(degree, N);
    fill_kernel<<<(E + 255) / 256, 256>>>(esrc, edst, E);
    gather_kernel<<<(N * 32 + 255) / 256, 256>>>(x, degree, N);

    cudaFuncSetAttribute(fused_kernel, cudaFuncAttributeMaxDynamicSharedMemorySize, SMEM_TOTAL);
    fused_kernel<<<(nrows + MTILE - 1) / MTILE, NTHREADS, SMEM_TOTAL>>>(
        x, sn_g, sn_b, nn_g, nn_b, b1, b2, (float*)d_out, nrows);
}

// round 7
// speedup vs baseline: 1.9150x; 1.3087x over previous
#include <cuda_runtime.h>
#include <cuda_bf16.h>
#include <cstdint>
#include <stdint.h>
#include <math.h>

#define D      128
#define TWO_D  256
#define MTILE  64
#define NTHREADS 256
#define MAXN   50000
#define MAXE   800000

// A image: 64 rows x 256 bf16, row stride 528 bytes (padded; conflict-free LDSM)
#define A_STRIDE 528
#define A_IMG    (64 * A_STRIDE)      // 33792
// B chunk rows: 80 bytes (32 bf16 + 16B pad)
#define SMEM_AHI 0
#define SMEM_ALO A_IMG
#define SMEM_BHI (2 * A_IMG)          // 67584
#define SMEM_BLO (SMEM_BHI + 20480)   // 88064
#define SMEM_TOTAL (SMEM_BLO + 20480) // 108544  (2 CTAs/SM: 217KB <= 228KB)

// ---------------------------------------------------------------------------
// Device globals
// ---------------------------------------------------------------------------
__device__ float g_neighbor[2 * MAXN * D];
__device__ int   g_base[MAXN + 1];
__device__ int   g_cursor[MAXN];
__device__ int   g_csr[MAXE];
// W1^T split images: [8 kchunks][256 n][80 B]  = 163840 B per term
__device__ uint4 g_B1hi[10240];
__device__ uint4 g_B1lo[10240];
// W2^T split images: [8 kchunks][128 n][80 B]  = 81920 B per term
__device__ uint4 g_B2hi[5120];
__device__ uint4 g_B2lo[5120];

// ---------------------------------------------------------------------------
// helpers
// ---------------------------------------------------------------------------
__device__ __forceinline__ uint32_t smem_u32(const void* p) {
    uint32_t a;
    asm("{ .reg .u64 t; cvta.to.shared.u64 t, %1; cvt.u32.u64 %0, t; }" : "=r"(a) : "l"(p));
    return a;
}
__device__ __forceinline__ void ldsm4(uint32_t* r, uint32_t addr) {
    asm volatile("ldmatrix.sync.aligned.m8n8.x4.shared.b16 {%0,%1,%2,%3}, [%4];"
                 : "=r"(r[0]), "=r"(r[1]), "=r"(r[2]), "=r"(r[3]) : "r"(addr));
}
__device__ __forceinline__ void mma16816(float* d, const uint32_t* a, const uint32_t* b) {
    asm volatile("mma.sync.aligned.m16n8k16.row.col.f32.bf16.bf16.f32 "
                 "{%0,%1,%2,%3}, {%4,%5,%6,%7}, {%8,%9}, {%0,%1,%2,%3};"
                 : "+f"(d[0]), "+f"(d[1]), "+f"(d[2]), "+f"(d[3])
                 : "r"(a[0]), "r"(a[1]), "r"(a[2]), "r"(a[3]), "r"(b[0]), "r"(b[1]));
}
// A-image byte offset (row-major, k contiguous within 16B segs)
__device__ __forceinline__ int a_off(int row, int k) {
    return row * A_STRIDE + ((k >> 3) << 4) + ((k & 7) << 1);
}
// B chunk-image byte offset (chunk_bytes = n_rows * 80)
__device__ __forceinline__ int b_off(int n, int k, int chunk_bytes) {
    return (k >> 5) * chunk_bytes + n * 80 + (((k & 31) >> 3) << 4) + ((k & 7) << 1);
}
__device__ __forceinline__ void split_pair(char* hi_base, char* lo_base, int off,
                                           float v0, float v1) {
    __nv_bfloat16 h0 = __float2bfloat16(v0);
    __nv_bfloat16 h1 = __float2bfloat16(v1);
    __nv_bfloat16 l0 = __float2bfloat16(v0 - __bfloat162float(h0));
    __nv_bfloat16 l1 = __float2bfloat16(v1 - __bfloat162float(h1));
    *reinterpret_cast<__nv_bfloat162*>(hi_base + off) = __halves2bfloat162(h0, h1);
    *reinterpret_cast<__nv_bfloat162*>(lo_base + off) = __halves2bfloat162(l0, l1);
}

// ---------------------------------------------------------------------------
// Prep: transpose + split weights into chunked images
// ---------------------------------------------------------------------------
__global__ void prep_w1(const float* __restrict__ W1) {
    int idx = blockIdx.x * blockDim.x + threadIdx.x;   // n*128 + kpair
    if (idx >= 256 * 128) return;
    int n = idx >> 7, k = (idx & 127) << 1;
    float w0 = W1[(size_t)k * 256 + n];
    float w1 = W1[(size_t)(k + 1) * 256 + n];
    split_pair((char*)g_B1hi, (char*)g_B1lo, b_off(n, k, 20480), w0, w1);
}
__global__ void prep_w2(const float* __restrict__ W2) {
    int idx = blockIdx.x * blockDim.x + threadIdx.x;   // n*128 + kpair
    if (idx >= 128 * 128) return;
    int n = idx >> 7, k = (idx & 127) << 1;
    float w0 = W2[(size_t)k * 128 + n];
    float w1 = W2[(size_t)(k + 1) * 128 + n];
    split_pair((char*)g_B2hi, (char*)g_B2lo, b_off(n, k, 10240), w0, w1);
}

// ---------------------------------------------------------------------------
// CSR build + gather (unchanged, proven)
// ---------------------------------------------------------------------------
__global__ void scan_kernel(const float* __restrict__ degree, int N) {
    __shared__ int warp_sums[32];
    __shared__ int s_carry;
    const int tid = threadIdx.x, lane = tid & 31, wid = tid >> 5;
    if (tid == 0) s_carry = 0;
    __syncthreads();
    for (int chunk = 0; chunk < N; chunk += 1024) {
        int i = chunk + tid;
        int v = (i < N) ? (int)degree[i] : 0;
        int inc = v;
#pragma unroll
        for (int o = 1; o < 32; o <<= 1) {
            int t = __shfl_up_sync(0xffffffffu, inc, o);
            if (lane >= o) inc += t;
        }
        if (lane == 31) warp_sums[wid] = inc;
        __syncthreads();
        if (wid == 0) {
            int ws = warp_sums[lane];
#pragma unroll
            for (int o = 1; o < 32; o <<= 1) {
                int t = __shfl_up_sync(0xffffffffu, ws, o);
                if (lane >= o) ws += t;
            }
            warp_sums[lane] = ws;
        }
        __syncthreads();
        int warp_prefix = (wid > 0) ? warp_sums[wid - 1] : 0;
        int excl = s_carry + warp_prefix + inc - v;
        if (i < N) { g_base[i] = excl; g_cursor[i] = 0; }
        __syncthreads();
        if (tid == 1023) s_carry += warp_sums[31];
        __syncthreads();
    }
    if (tid == 0) g_base[N] = s_carry;
}

__global__ void fill_kernel(const int* __restrict__ esrc,
                            const int* __restrict__ edst, int E) {
    int e = blockIdx.x * blockDim.x + threadIdx.x;
    if (e >= E) return;
    int t = edst[e];
    int pos = g_base[t] + atomicAdd(&g_cursor[t], 1);
    if (pos < MAXE) g_csr[pos] = esrc[e];
}

__global__ void gather_kernel(const float* __restrict__ x,
                              const float* __restrict__ degree, int N) {
    int n = (blockIdx.x * blockDim.x + threadIdx.x) >> 5;
    int lane = threadIdx.x & 31;
    if (n >= N) return;
    int   deg = (int)degree[n];
    float inv = 1.0f / fmaxf(degree[n], 1.0f);
    int   b0  = g_base[n];
    float4 a0 = make_float4(0.f, 0.f, 0.f, 0.f);
    float4 a1 = make_float4(0.f, 0.f, 0.f, 0.f);
    int j = 0;
    for (; j + 2 <= deg; j += 2) {
        int s0 = g_csr[b0 + j], s1 = g_csr[b0 + j + 1];
        const float4 v00 = *reinterpret_cast<const float4*>(x + (size_t)s0 * D + lane * 4);
        const float4 v01 = *reinterpret_cast<const float4*>(x + ((size_t)(N + s0)) * D + lane * 4);
        const float4 v10 = *reinterpret_cast<const float4*>(x + (size_t)s1 * D + lane * 4);
        const float4 v11 = *reinterpret_cast<const float4*>(x + ((size_t)(N + s1)) * D + lane * 4);
        a0.x += v00.x + v10.x; a0.y += v00.y + v10.y;
        a0.z += v00.z + v10.z; a0.w += v00.w + v10.w;
        a1.x += v01.x + v11.x; a1.y += v01.y + v11.y;
        a1.z += v01.z + v11.z; a1.w += v01.w + v11.w;
    }
    if (j < deg) {
        int s0 = g_csr[b0 + j];
        const float4 v00 = *reinterpret_cast<const float4*>(x + (size_t)s0 * D + lane * 4);
        const float4 v01 = *reinterpret_cast<const float4*>(x + ((size_t)(N + s0)) * D + lane * 4);
        a0.x += v00.x; a0.y += v00.y; a0.z += v00.z; a0.w += v00.w;
        a1.x += v01.x; a1.y += v01.y; a1.z += v01.z; a1.w += v01.w;
    }
    a0.x *= inv; a0.y *= inv; a0.z *= inv; a0.w *= inv;
    a1.x *= inv; a1.y *= inv; a1.z *= inv; a1.w *= inv;
    *reinterpret_cast<float4*>(g_neighbor + (size_t)n * D + lane * 4)         = a0;
    *reinterpret_cast<float4*>(g_neighbor + ((size_t)(N + n)) * D + lane * 4) = a1;
}

// ---------------------------------------------------------------------------
// Fused kernel: LN -> split-bf16 mma.sync GEMM1 -> GELU -> GEMM2 -> +x
// 64 rows/CTA, 8 warps: wm = warp&1 (2 in M), wn = warp>>1 (4 in N)
// 2 CTAs/SM so co-resident CTAs overlap each other's stage/sync/LN bubbles.
// ---------------------------------------------------------------------------
__global__ void __launch_bounds__(NTHREADS, 2)
fused_kernel(const float* __restrict__ x,
             const float* __restrict__ sn_g, const float* __restrict__ sn_b,
             const float* __restrict__ nn_g, const float* __restrict__ nn_b,
             const float* __restrict__ b1,  const float* __restrict__ b2,
             float* __restrict__ out, int nrows) {
    extern __shared__ char sm[];
    const uint32_t smem_base = smem_u32(sm);
    char* Ahi = sm + SMEM_AHI;
    char* Alo = sm + SMEM_ALO;

    const int tid  = threadIdx.x;
    const int lane = tid & 31;
    const int warp = tid >> 5;
    const int wm   = warp & 1;
    const int wn   = warp >> 1;
    const int row0 = blockIdx.x * MTILE;
    const int g    = lane >> 3;     // ldmatrix tile group
    const int lr   = lane & 7;

    // ---------------- Stage 1: LayerNorms -> A_hi/A_lo images ---------------
    {
        const float4 g1  = *reinterpret_cast<const float4*>(sn_g + lane * 4);
        const float4 be1 = *reinterpret_cast<const float4*>(sn_b + lane * 4);
        const float4 g2  = *reinterpret_cast<const float4*>(nn_g + lane * 4);
        const float4 be2 = *reinterpret_cast<const float4*>(nn_b + lane * 4);
        const int k0 = lane * 4;
#pragma unroll
        for (int rr = 0; rr < 8; rr++) {
            const int r    = warp * 8 + rr;
            const int grow = row0 + r;
            if (grow < nrows) {
                float4 xv = *reinterpret_cast<const float4*>(x + (size_t)grow * D + k0);
                float sum  = xv.x + xv.y + xv.z + xv.w;
                float sumq = xv.x * xv.x + xv.y * xv.y + xv.z * xv.z + xv.w * xv.w;
#pragma unroll
                for (int o = 16; o > 0; o >>= 1) {
                    sum  += __shfl_xor_sync(0xffffffffu, sum, o);
                    sumq += __shfl_xor_sync(0xffffffffu, sumq, o);
                }
                float mn   = sum * (1.0f / 128.0f);
                float rstd = rsqrtf(sumq * (1.0f / 128.0f) - mn * mn + 1e-5f);
                split_pair(Ahi, Alo, a_off(r, k0),     (xv.x - mn) * rstd * g1.x + be1.x,
                                                       (xv.y - mn) * rstd * g1.y + be1.y);
                split_pair(Ahi, Alo, a_off(r, k0 + 2), (xv.z - mn) * rstd * g1.z + be1.z,
                                                       (xv.w - mn) * rstd * g1.w + be1.w);
                float4 nv = *reinterpret_cast<const float4*>(g_neighbor + (size_t)grow * D + k0);
                sum  = nv.x + nv.y + nv.z + nv.w;
                sumq = nv.x * nv.x + nv.y * nv.y + nv.z * nv.z + nv.w * nv.w;
#pragma unroll
                for (int o = 16; o > 0; o >>= 1) {
                    sum  += __shfl_xor_sync(0xffffffffu, sum, o);
                    sumq += __shfl_xor_sync(0xffffffffu, sumq, o);
                }
                mn   = sum * (1.0f / 128.0f);
                rstd = rsqrtf(sumq * (1.0f / 128.0f) - mn * mn + 1e-5f);
                split_pair(Ahi, Alo, a_off(r, 128 + k0),     (nv.x - mn) * rstd * g2.x + be2.x,
                                                             (nv.y - mn) * rstd * g2.y + be2.y);
                split_pair(Ahi, Alo, a_off(r, 128 + k0 + 2), (nv.z - mn) * rstd * g2.z + be2.z,
                                                             (nv.w - mn) * rstd * g2.w + be2.w);
            } else {
                split_pair(Ahi, Alo, a_off(r, k0),           0.f, 0.f);
                split_pair(Ahi, Alo, a_off(r, k0 + 2),       0.f, 0.f);
                split_pair(Ahi, Alo, a_off(r, 128 + k0),     0.f, 0.f);
                split_pair(Ahi, Alo, a_off(r, 128 + k0 + 2), 0.f, 0.f);
            }
        }
    }

    // ---------------- Stage 2: GEMM1 (64 x 256 x 256, 3 split terms) --------
    float acc[2][8][4];
#pragma unroll
    for (int i = 0; i < 2; i++)
#pragma unroll
        for (int j = 0; j < 8; j++)
#pragma unroll
            for (int r = 0; r < 4; r++) acc[i][j][r] = 0.f;

    for (int kc = 0; kc < 8; kc++) {
        __syncthreads();
        {
            uint4* dhi = reinterpret_cast<uint4*>(sm + SMEM_BHI);
            uint4* dlo = reinterpret_cast<uint4*>(sm + SMEM_BLO);
#pragma unroll
            for (int it = 0; it < 5; it++) {
                int i = it * NTHREADS + tid;
                dhi[i] = g_B1hi[kc * 1280 + i];
                dlo[i] = g_B1lo[kc * 1280 + i];
            }
        }
        __syncthreads();
#pragma unroll
        for (int ks = 0; ks < 2; ks++) {
            const int kabs = kc * 32 + ks * 16;
            uint32_t ahi[2][4], alo[2][4];
#pragma unroll
            for (int ti = 0; ti < 2; ti++) {
                int row = wm * 32 + ti * 16 + (g & 1) * 8 + lr;
                uint32_t off = row * A_STRIDE + (((kabs >> 3) + (g >> 1)) << 4);
                ldsm4(ahi[ti], smem_base + SMEM_AHI + off);
                ldsm4(alo[ti], smem_base + SMEM_ALO + off);
            }
#pragma unroll
            for (int jj = 0; jj < 4; jj++) {
                int n = wn * 64 + jj * 16 + (g >> 1) * 8 + lr;
                uint32_t boff = n * 80 + (((ks * 16 >> 3) + (g & 1)) << 4);
                uint32_t bhi[4], blo[4];
                ldsm4(bhi, smem_base + SMEM_BHI + boff);
                ldsm4(blo, smem_base + SMEM_BLO + boff);
#pragma unroll
                for (int ti = 0; ti < 2; ti++) {
                    mma16816(acc[ti][2 * jj],     ahi[ti], bhi);
                    mma16816(acc[ti][2 * jj],     ahi[ti], blo);
                    mma16816(acc[ti][2 * jj],     alo[ti], bhi);
                    mma16816(acc[ti][2 * jj + 1], ahi[ti], bhi + 2);
                    mma16816(acc[ti][2 * jj + 1], ahi[ti], blo + 2);
                    mma16816(acc[ti][2 * jj + 1], alo[ti], bhi + 2);
                }
            }
        }
    }

    // ---------------- Stage 3: bias + GELU -> A2 images (reuse A bufs) ------
    __syncthreads();
#pragma unroll
    for (int tj = 0; tj < 8; tj++) {
        const int col = wn * 64 + tj * 8 + (lane & 3) * 2;
        const float2 bb = *reinterpret_cast<const float2*>(b1 + col);
#pragma unroll
        for (int ti = 0; ti < 2; ti++)
#pragma unroll
            for (int rp = 0; rp < 2; rp++) {
                int row = wm * 32 + ti * 16 + (lane >> 2) + rp * 8;
                float v0 = acc[ti][tj][rp * 2 + 0] + bb.x;
                float v1 = acc[ti][tj][rp * 2 + 1] + bb.y;
                v0 = 0.5f * v0 * (1.0f + erff(v0 * 0.70710678118654752f));
                v1 = 0.5f * v1 * (1.0f + erff(v1 * 0.70710678118654752f));
                split_pair(Ahi, Alo, a_off(row, col), v0, v1);
            }
    }

    // ---------------- Stage 4: GEMM2 (64 x 128 x 256, 3 split terms) --------
    float c2[2][4][4];
#pragma unroll
    for (int i = 0; i < 2; i++)
#pragma unroll
        for (int j = 0; j < 4; j++)
#pragma unroll
            for (int r = 0; r < 4; r++) c2[i][j][r] = 0.f;

    for (int kc = 0; kc < 8; kc++) {
        __syncthreads();
        {
            uint4* dhi = reinterpret_cast<uint4*>(sm + SMEM_BHI);
            uint4* dlo = reinterpret_cast<uint4*>(sm + SMEM_BLO);
            for (int i = tid; i < 640; i += NTHREADS) {
                dhi[i] = g_B2hi[kc * 640 + i];
                dlo[i] = g_B2lo[kc * 640 + i];
            }
        }
        __syncthreads();
#pragma unroll
        for (int ks = 0; ks < 2; ks++) {
            const int kabs = kc * 32 + ks * 16;
            uint32_t ahi[2][4], alo[2][4];
#pragma unroll
            for (int ti = 0; ti < 2; ti++) {
                int row = wm * 32 + ti * 16 + (g & 1) * 8 + lr;
                uint32_t off = row * A_STRIDE + (((kabs >> 3) + (g >> 1)) << 4);
                ldsm4(ahi[ti], smem_base + SMEM_AHI + off);
                ldsm4(alo[ti], smem_base + SMEM_ALO + off);
            }
#pragma unroll
            for (int jj = 0; jj < 2; jj++) {
                int n = wn * 32 + jj * 16 + (g >> 1) * 8 + lr;
                uint32_t boff = n * 80 + (((ks * 16 >> 3) + (g & 1)) << 4);
                uint32_t bhi[4], blo[4];
                ldsm4(bhi, smem_base + SMEM_BHI + boff);
                ldsm4(blo, smem_base + SMEM_BLO + boff);
#pragma unroll
                for (int ti = 0; ti < 2; ti++) {
                    mma16816(c2[ti][2 * jj],     ahi[ti], bhi);
                    mma16816(c2[ti][2 * jj],     ahi[ti], blo);
                    mma16816(c2[ti][2 * jj],     alo[ti], bhi);
                    mma16816(c2[ti][2 * jj + 1], ahi[ti], bhi + 2);
                    mma16816(c2[ti][2 * jj + 1], ahi[ti], blo + 2);
                    mma16816(c2[ti][2 * jj + 1], alo[ti], bhi + 2);
                }
            }
        }
    }

    // ---------------- Stage 5: bias + residual + store ----------------------
#pragma unroll
    for (int tj = 0; tj < 4; tj++) {
        const int col = wn * 32 + tj * 8 + (lane & 3) * 2;
        const float2 bb = *reinterpret_cast<const float2*>(b2 + col);
#pragma unroll
        for (int ti = 0; ti < 2; ti++)
#pragma unroll
            for (int rp = 0; rp < 2; rp++) {
                int row  = wm * 32 + ti * 16 + (lane >> 2) + rp * 8;
                int grow = row0 + row;
                if (grow < nrows) {
                    const float2 xv = *reinterpret_cast<const float2*>(x + (size_t)grow * D + col);
                    float2 o;
                    o.x = xv.x + c2[ti][tj][rp * 2 + 0] + bb.x;
                    o.y = xv.y + c2[ti][tj][rp * 2 + 1] + bb.y;
                    *reinterpret_cast<float2*>(out + (size_t)grow * D + col) = o;
                }
            }
    }
}

// ---------------------------------------------------------------------------
extern "C" void kernel_launch(void* const* d_in, const int* in_sizes, int n_in,
                              void* d_out, int out_size) {
    const float* x      = (const float*)d_in[0];
    const int*   esrc   = (const int*)  d_in[1];
    const int*   edst   = (const int*)  d_in[2];
    const float* degree = (const float*)d_in[3];
    const float* sn_g   = (const float*)d_in[4];
    const float* sn_b   = (const float*)d_in[5];
    const float* nn_g   = (const float*)d_in[6];
    const float* nn_b   = (const float*)d_in[7];
    const float* W1     = (const float*)d_in[8];
    const float* b1     = (const float*)d_in[9];
    const float* W2     = (const float*)d_in[10];
    const float* b2     = (const float*)d_in[11];

    const int E     = in_sizes[1];
    const int nrows = in_sizes[0] / D;   // B*N
    const int N     = in_sizes[3];

    prep_w1<<<(256 * 128 + 255) / 256, 256>>>(W1);
    prep_w2<<<(128 * 128 + 255) / 256, 256>>>(W2);
    scan_kernel<<<1, 1024>>>(degree, N);
    fill_kernel<<<(E + 255) / 256, 256>>>(esrc, edst, E);
    gather_kernel<<<(N * 32 + 255) / 256, 256>>>(x, degree, N);

    cudaFuncSetAttribute(fused_kernel, cudaFuncAttributeMaxDynamicSharedMemorySize, SMEM_TOTAL);
    fused_kernel<<<(nrows + MTILE - 1) / MTILE, NTHREADS, SMEM_TOTAL>>>(
        x, sn_g, sn_b, nn_g, nn_b, b1, b2, (float*)d_out, nrows);
}

// round 8
// speedup vs baseline: 2.3655x; 1.2353x over previous
#include <cuda_runtime.h>
#include <cuda_bf16.h>
#include <cstdint>
#include <stdint.h>
#include <math.h>

#define D      128
#define TWO_D  256
#define MTILE  64
#define NTHREADS 256
#define MAXN   50000
#define MAXE   800000

// A image: 64 rows x 256 bf16, row stride 528 bytes (conflict-free LDSM)
#define A_STRIDE 528
#define A_IMG    (64 * A_STRIDE)      // 33792
#define SMEM_AHI 0
#define SMEM_ALO A_IMG
#define SMEM_TOTAL (2 * A_IMG)        // 67584 -> 2 CTAs/SM easily

// ---------------------------------------------------------------------------
// Device globals
// ---------------------------------------------------------------------------
__device__ float g_neighbor[2 * MAXN * D];
__device__ int   g_base[MAXN + 1];
__device__ int   g_cursor[MAXN];
__device__ int   g_csr[MAXE];
// Pre-computed mma.sync B fragments (per-lane register images), hi/lo terms.
// B1 (W1^T, 256n x 256k): [16 ks][16 ng][32 lanes] uint4
__device__ uint4 g_B1fh[8192];
__device__ uint4 g_B1fl[8192];
// B2 (W2^T, 128n x 256k): [16 ks][8 ng][32 lanes] uint4
__device__ uint4 g_B2fh[4096];
__device__ uint4 g_B2fl[4096];

// ---------------------------------------------------------------------------
// helpers
// ---------------------------------------------------------------------------
__device__ __forceinline__ uint32_t smem_u32(const void* p) {
    uint32_t a;
    asm("{ .reg .u64 t; cvta.to.shared.u64 t, %1; cvt.u32.u64 %0, t; }" : "=r"(a) : "l"(p));
    return a;
}
__device__ __forceinline__ void ldsm4(uint32_t* r, uint32_t addr) {
    asm volatile("ldmatrix.sync.aligned.m8n8.x4.shared.b16 {%0,%1,%2,%3}, [%4];"
                 : "=r"(r[0]), "=r"(r[1]), "=r"(r[2]), "=r"(r[3]) : "r"(addr));
}
__device__ __forceinline__ void mma16816(float* d, const uint32_t* a, uint32_t b0, uint32_t b1) {
    asm volatile("mma.sync.aligned.m16n8k16.row.col.f32.bf16.bf16.f32 "
                 "{%0,%1,%2,%3}, {%4,%5,%6,%7}, {%8,%9}, {%0,%1,%2,%3};"
                 : "+f"(d[0]), "+f"(d[1]), "+f"(d[2]), "+f"(d[3])
                 : "r"(a[0]), "r"(a[1]), "r"(a[2]), "r"(a[3]), "r"(b0), "r"(b1));
}
// A-image byte offset (row-major, k contiguous within 16B segs)
__device__ __forceinline__ int a_off(int row, int k) {
    return row * A_STRIDE + ((k >> 3) << 4) + ((k & 7) << 1);
}
__device__ __forceinline__ void split_pair(char* hi_base, char* lo_base, int off,
                                           float v0, float v1) {
    __nv_bfloat16 h0 = __float2bfloat16(v0);
    __nv_bfloat16 h1 = __float2bfloat16(v1);
    __nv_bfloat16 l0 = __float2bfloat16(v0 - __bfloat162float(h0));
    __nv_bfloat16 l1 = __float2bfloat16(v1 - __bfloat162float(h1));
    *reinterpret_cast<__nv_bfloat162*>(hi_base + off) = __halves2bfloat162(h0, h1);
    *reinterpret_cast<__nv_bfloat162*>(lo_base + off) = __halves2bfloat162(l0, l1);
}
__device__ __forceinline__ uint32_t pack_hi(float a, float b) {
    __nv_bfloat162 v = __halves2bfloat162(__float2bfloat16(a), __float2bfloat16(b));
    return *reinterpret_cast<uint32_t*>(&v);
}
__device__ __forceinline__ uint32_t pack_lo(float a, float b) {
    __nv_bfloat16 ha = __float2bfloat16(a), hb = __float2bfloat16(b);
    __nv_bfloat162 v = __halves2bfloat162(__float2bfloat16(a - __bfloat162float(ha)),
                                          __float2bfloat16(b - __bfloat162float(hb)));
    return *reinterpret_cast<uint32_t*>(&v);
}

// ---------------------------------------------------------------------------
// Prep: weights -> per-lane mma B fragments (hi/lo split)
// Fragment (ks, ng, lane): n0 = ng*16 + lane/4, kb = ks*16 + (lane%4)*2
//   .x: B[n0][kb,kb+1]  .y: B[n0][kb+8,kb+9]
//   .z: B[n0+8][kb..]   .w: B[n0+8][kb+8..]      (B[n][k] = W[k][n])
// ---------------------------------------------------------------------------
__global__ void prep_w1(const float* __restrict__ W1) {
    int idx = blockIdx.x * blockDim.x + threadIdx.x;
    if (idx >= 8192) return;
    int lane = idx & 31, ng = (idx >> 5) & 15, ks = idx >> 9;
    int n0 = ng * 16 + (lane >> 2);
    int kb = ks * 16 + (lane & 3) * 2;
    float a0 = W1[(size_t)(kb)     * 256 + n0], a1 = W1[(size_t)(kb + 1) * 256 + n0];
    float a2 = W1[(size_t)(kb + 8) * 256 + n0], a3 = W1[(size_t)(kb + 9) * 256 + n0];
    float a4 = W1[(size_t)(kb)     * 256 + n0 + 8], a5 = W1[(size_t)(kb + 1) * 256 + n0 + 8];
    float a6 = W1[(size_t)(kb + 8) * 256 + n0 + 8], a7 = W1[(size_t)(kb + 9) * 256 + n0 + 8];
    g_B1fh[idx] = make_uint4(pack_hi(a0, a1), pack_hi(a2, a3), pack_hi(a4, a5), pack_hi(a6, a7));
    g_B1fl[idx] = make_uint4(pack_lo(a0, a1), pack_lo(a2, a3), pack_lo(a4, a5), pack_lo(a6, a7));
}
__global__ void prep_w2(const float* __restrict__ W2) {
    int idx = blockIdx.x * blockDim.x + threadIdx.x;
    if (idx >= 4096) return;
    int lane = idx & 31, ng = (idx >> 5) & 7, ks = idx >> 8;
    int n0 = ng * 16 + (lane >> 2);
    int kb = ks * 16 + (lane & 3) * 2;
    float a0 = W2[(size_t)(kb)     * 128 + n0], a1 = W2[(size_t)(kb + 1) * 128 + n0];
    float a2 = W2[(size_t)(kb + 8) * 128 + n0], a3 = W2[(size_t)(kb + 9) * 128 + n0];
    float a4 = W2[(size_t)(kb)     * 128 + n0 + 8], a5 = W2[(size_t)(kb + 1) * 128 + n0 + 8];
    float a6 = W2[(size_t)(kb + 8) * 128 + n0 + 8], a7 = W2[(size_t)(kb + 9) * 128 + n0 + 8];
    g_B2fh[idx] = make_uint4(pack_hi(a0, a1), pack_hi(a2, a3), pack_hi(a4, a5), pack_hi(a6, a7));
    g_B2fl[idx] = make_uint4(pack_lo(a0, a1), pack_lo(a2, a3), pack_lo(a4, a5), pack_lo(a6, a7));
}

// ---------------------------------------------------------------------------
// CSR build + gather (unchanged, proven)
// ---------------------------------------------------------------------------
__global__ void scan_kernel(const float* __restrict__ degree, int N) {
    __shared__ int warp_sums[32];
    __shared__ int s_carry;
    const int tid = threadIdx.x, lane = tid & 31, wid = tid >> 5;
    if (tid == 0) s_carry = 0;
    __syncthreads();
    for (int chunk = 0; chunk < N; chunk += 1024) {
        int i = chunk + tid;
        int v = (i < N) ? (int)degree[i] : 0;
        int inc = v;
#pragma unroll
        for (int o = 1; o < 32; o <<= 1) {
            int t = __shfl_up_sync(0xffffffffu, inc, o);
            if (lane >= o) inc += t;
        }
        if (lane == 31) warp_sums[wid] = inc;
        __syncthreads();
        if (wid == 0) {
            int ws = warp_sums[lane];
#pragma unroll
            for (int o = 1; o < 32; o <<= 1) {
                int t = __shfl_up_sync(0xffffffffu, ws, o);
                if (lane >= o) ws += t;
            }
            warp_sums[lane] = ws;
        }
        __syncthreads();
        int warp_prefix = (wid > 0) ? warp_sums[wid - 1] : 0;
        int excl = s_carry + warp_prefix + inc - v;
        if (i < N) { g_base[i] = excl; g_cursor[i] = 0; }
        __syncthreads();
        if (tid == 1023) s_carry += warp_sums[31];
        __syncthreads();
    }
    if (tid == 0) g_base[N] = s_carry;
}

__global__ void fill_kernel(const int* __restrict__ esrc,
                            const int* __restrict__ edst, int E) {
    int e = blockIdx.x * blockDim.x + threadIdx.x;
    if (e >= E) return;
    int t = edst[e];
    int pos = g_base[t] + atomicAdd(&g_cursor[t], 1);
    if (pos < MAXE) g_csr[pos] = esrc[e];
}

__global__ void gather_kernel(const float* __restrict__ x,
                              const float* __restrict__ degree, int N) {
    int n = (blockIdx.x * blockDim.x + threadIdx.x) >> 5;
    int lane = threadIdx.x & 31;
    if (n >= N) return;
    int   deg = (int)degree[n];
    float inv = 1.0f / fmaxf(degree[n], 1.0f);
    int   b0  = g_base[n];
    float4 a0 = make_float4(0.f, 0.f, 0.f, 0.f);
    float4 a1 = make_float4(0.f, 0.f, 0.f, 0.f);
    int j = 0;
    for (; j + 2 <= deg; j += 2) {
        int s0 = g_csr[b0 + j], s1 = g_csr[b0 + j + 1];
        const float4 v00 = *reinterpret_cast<const float4*>(x + (size_t)s0 * D + lane * 4);
        const float4 v01 = *reinterpret_cast<const float4*>(x + ((size_t)(N + s0)) * D + lane * 4);
        const float4 v10 = *reinterpret_cast<const float4*>(x + (size_t)s1 * D + lane * 4);
        const float4 v11 = *reinterpret_cast<const float4*>(x + ((size_t)(N + s1)) * D + lane * 4);
        a0.x += v00.x + v10.x; a0.y += v00.y + v10.y;
        a0.z += v00.z + v10.z; a0.w += v00.w + v10.w;
        a1.x += v01.x + v11.x; a1.y += v01.y + v11.y;
        a1.z += v01.z + v11.z; a1.w += v01.w + v11.w;
    }
    if (j < deg) {
        int s0 = g_csr[b0 + j];
        const float4 v00 = *reinterpret_cast<const float4*>(x + (size_t)s0 * D + lane * 4);
        const float4 v01 = *reinterpret_cast<const float4*>(x + ((size_t)(N + s0)) * D + lane * 4);
        a0.x += v00.x; a0.y += v00.y; a0.z += v00.z; a0.w += v00.w;
        a1.x += v01.x; a1.y += v01.y; a1.z += v01.z; a1.w += v01.w;
    }
    a0.x *= inv; a0.y *= inv; a0.z *= inv; a0.w *= inv;
    a1.x *= inv; a1.y *= inv; a1.z *= inv; a1.w *= inv;
    *reinterpret_cast<float4*>(g_neighbor + (size_t)n * D + lane * 4)         = a0;
    *reinterpret_cast<float4*>(g_neighbor + ((size_t)(N + n)) * D + lane * 4) = a1;
}

// ---------------------------------------------------------------------------
// Fused kernel: LN -> split-bf16 mma.sync GEMM1 -> GELU -> GEMM2 -> +x
// B operands come straight from gmem fragments (L2-resident) - no staging,
// no mainloop barriers. 2 CTAs/SM.
// ---------------------------------------------------------------------------
__global__ void __launch_bounds__(NTHREADS, 2)
fused_kernel(const float* __restrict__ x,
             const float* __restrict__ sn_g, const float* __restrict__ sn_b,
             const float* __restrict__ nn_g, const float* __restrict__ nn_b,
             const float* __restrict__ b1,  const float* __restrict__ b2,
             float* __restrict__ out, int nrows) {
    extern __shared__ char sm[];
    const uint32_t smem_base = smem_u32(sm);
    char* Ahi = sm + SMEM_AHI;
    char* Alo = sm + SMEM_ALO;

    const int tid  = threadIdx.x;
    const int lane = tid & 31;
    const int warp = tid >> 5;
    const int wm   = warp & 1;
    const int wn   = warp >> 1;
    const int row0 = blockIdx.x * MTILE;
    const int g    = lane >> 3;
    const int lr   = lane & 7;

    // ---------------- Stage 1: LayerNorms -> A_hi/A_lo images ---------------
    {
        const float4 g1  = *reinterpret_cast<const float4*>(sn_g + lane * 4);
        const float4 be1 = *reinterpret_cast<const float4*>(sn_b + lane * 4);
        const float4 g2  = *reinterpret_cast<const float4*>(nn_g + lane * 4);
        const float4 be2 = *reinterpret_cast<const float4*>(nn_b + lane * 4);
        const int k0 = lane * 4;
#pragma unroll
        for (int rr = 0; rr < 8; rr++) {
            const int r    = warp * 8 + rr;
            const int grow = row0 + r;
            if (grow < nrows) {
                float4 xv = *reinterpret_cast<const float4*>(x + (size_t)grow * D + k0);
                float sum  = xv.x + xv.y + xv.z + xv.w;
                float sumq = xv.x * xv.x + xv.y * xv.y + xv.z * xv.z + xv.w * xv.w;
#pragma unroll
                for (int o = 16; o > 0; o >>= 1) {
                    sum  += __shfl_xor_sync(0xffffffffu, sum, o);
                    sumq += __shfl_xor_sync(0xffffffffu, sumq, o);
                }
                float mn   = sum * (1.0f / 128.0f);
                float rstd = rsqrtf(sumq * (1.0f / 128.0f) - mn * mn + 1e-5f);
                split_pair(Ahi, Alo, a_off(r, k0),     (xv.x - mn) * rstd * g1.x + be1.x,
                                                       (xv.y - mn) * rstd * g1.y + be1.y);
                split_pair(Ahi, Alo, a_off(r, k0 + 2), (xv.z - mn) * rstd * g1.z + be1.z,
                                                       (xv.w - mn) * rstd * g1.w + be1.w);
                float4 nv = *reinterpret_cast<const float4*>(g_neighbor + (size_t)grow * D + k0);
                sum  = nv.x + nv.y + nv.z + nv.w;
                sumq = nv.x * nv.x + nv.y * nv.y + nv.z * nv.z + nv.w * nv.w;
#pragma unroll
                for (int o = 16; o > 0; o >>= 1) {
                    sum  += __shfl_xor_sync(0xffffffffu, sum, o);
                    sumq += __shfl_xor_sync(0xffffffffu, sumq, o);
                }
                mn   = sum * (1.0f / 128.0f);
                rstd = rsqrtf(sumq * (1.0f / 128.0f) - mn * mn + 1e-5f);
                split_pair(Ahi, Alo, a_off(r, 128 + k0),     (nv.x - mn) * rstd * g2.x + be2.x,
                                                             (nv.y - mn) * rstd * g2.y + be2.y);
                split_pair(Ahi, Alo, a_off(r, 128 + k0 + 2), (nv.z - mn) * rstd * g2.z + be2.z,
                                                             (nv.w - mn) * rstd * g2.w + be2.w);
            } else {
                split_pair(Ahi, Alo, a_off(r, k0),           0.f, 0.f);
                split_pair(Ahi, Alo, a_off(r, k0 + 2),       0.f, 0.f);
                split_pair(Ahi, Alo, a_off(r, 128 + k0),     0.f, 0.f);
                split_pair(Ahi, Alo, a_off(r, 128 + k0 + 2), 0.f, 0.f);
            }
        }
    }
    __syncthreads();

    // ---------------- Stage 2: GEMM1 (64 x 256 x 256, 3 split terms) --------
    float acc[2][8][4];
#pragma unroll
    for (int i = 0; i < 2; i++)
#pragma unroll
        for (int j = 0; j < 8; j++)
#pragma unroll
            for (int r = 0; r < 4; r++) acc[i][j][r] = 0.f;

#pragma unroll 2
    for (int ks = 0; ks < 16; ks++) {
        const int kabs = ks * 16;
        uint32_t ahi[2][4], alo[2][4];
#pragma unroll
        for (int ti = 0; ti < 2; ti++) {
            int row = wm * 32 + ti * 16 + (g & 1) * 8 + lr;
            uint32_t off = row * A_STRIDE + (((kabs >> 3) + (g >> 1)) << 4);
            ldsm4(ahi[ti], smem_base + SMEM_AHI + off);
            ldsm4(alo[ti], smem_base + SMEM_ALO + off);
        }
#pragma unroll
        for (int jj = 0; jj < 4; jj++) {
            const int fi = (ks * 16 + wn * 4 + jj) * 32 + lane;
            const uint4 fh = g_B1fh[fi];
            const uint4 fl = g_B1fl[fi];
#pragma unroll
            for (int ti = 0; ti < 2; ti++) {
                mma16816(acc[ti][2 * jj],     ahi[ti], fh.x, fh.y);
                mma16816(acc[ti][2 * jj],     ahi[ti], fl.x, fl.y);
                mma16816(acc[ti][2 * jj],     alo[ti], fh.x, fh.y);
                mma16816(acc[ti][2 * jj + 1], ahi[ti], fh.z, fh.w);
                mma16816(acc[ti][2 * jj + 1], ahi[ti], fl.z, fl.w);
                mma16816(acc[ti][2 * jj + 1], alo[ti], fh.z, fh.w);
            }
        }
    }

    // ---------------- Stage 3: bias + GELU -> A2 images (reuse A bufs) ------
    __syncthreads();
#pragma unroll
    for (int tj = 0; tj < 8; tj++) {
        const int col = wn * 64 + tj * 8 + (lane & 3) * 2;
        const float2 bb = *reinterpret_cast<const float2*>(b1 + col);
#pragma unroll
        for (int ti = 0; ti < 2; ti++)
#pragma unroll
            for (int rp = 0; rp < 2; rp++) {
                int row = wm * 32 + ti * 16 + (lane >> 2) + rp * 8;
                float v0 = acc[ti][tj][rp * 2 + 0] + bb.x;
                float v1 = acc[ti][tj][rp * 2 + 1] + bb.y;
                v0 = 0.5f * v0 * (1.0f + erff(v0 * 0.70710678118654752f));
                v1 = 0.5f * v1 * (1.0f + erff(v1 * 0.70710678118654752f));
                split_pair(Ahi, Alo, a_off(row, col), v0, v1);
            }
    }
    __syncthreads();

    // ---------------- Stage 4: GEMM2 (64 x 128 x 256, 3 split terms) --------
    float c2[2][4][4];
#pragma unroll
    for (int i = 0; i < 2; i++)
#pragma unroll
        for (int j = 0; j < 4; j++)
#pragma unroll
            for (int r = 0; r < 4; r++) c2[i][j][r] = 0.f;

#pragma unroll 2
    for (int ks = 0; ks < 16; ks++) {
        const int kabs = ks * 16;
        uint32_t ahi[2][4], alo[2][4];
#pragma unroll
        for (int ti = 0; ti < 2; ti++) {
            int row = wm * 32 + ti * 16 + (g & 1) * 8 + lr;
            uint32_t off = row * A_STRIDE + (((kabs >> 3) + (g >> 1)) << 4);
            ldsm4(ahi[ti], smem_base + SMEM_AHI + off);
            ldsm4(alo[ti], smem_base + SMEM_ALO + off);
        }
#pragma unroll
        for (int jj = 0; jj < 2; jj++) {
            const int fi = (ks * 8 + wn * 2 + jj) * 32 + lane;
            const uint4 fh = g_B2fh[fi];
            const uint4 fl = g_B2fl[fi];
#pragma unroll
            for (int ti = 0; ti < 2; ti++) {
                mma16816(c2[ti][2 * jj],     ahi[ti], fh.x, fh.y);
                mma16816(c2[ti][2 * jj],     ahi[ti], fl.x, fl.y);
                mma16816(c2[ti][2 * jj],     alo[ti], fh.x, fh.y);
                mma16816(c2[ti][2 * jj + 1], ahi[ti], fh.z, fh.w);
                mma16816(c2[ti][2 * jj + 1], ahi[ti], fl.z, fl.w);
                mma16816(c2[ti][2 * jj + 1], alo[ti], fh.z, fh.w);
            }
        }
    }

    // ---------------- Stage 5: bias + residual + store ----------------------
#pragma unroll
    for (int tj = 0; tj < 4; tj++) {
        const int col = wn * 32 + tj * 8 + (lane & 3) * 2;
        const float2 bb = *reinterpret_cast<const float2*>(b2 + col);
#pragma unroll
        for (int ti = 0; ti < 2; ti++)
#pragma unroll
            for (int rp = 0; rp < 2; rp++) {
                int row  = wm * 32 + ti * 16 + (lane >> 2) + rp * 8;
                int grow = row0 + row;
                if (grow < nrows) {
                    const float2 xv = *reinterpret_cast<const float2*>(x + (size_t)grow * D + col);
                    float2 o;
                    o.x = xv.x + c2[ti][tj][rp * 2 + 0] + bb.x;
                    o.y = xv.y + c2[ti][tj][rp * 2 + 1] + bb.y;
                    *reinterpret_cast<float2*>(out + (size_t)grow * D + col) = o;
                }
            }
    }
}

// ---------------------------------------------------------------------------
extern "C" void kernel_launch(void* const* d_in, const int* in_sizes, int n_in,
                              void* d_out, int out_size) {
    const float* x      = (const float*)d_in[0];
    const int*   esrc   = (const int*)  d_in[1];
    const int*   edst   = (const int*)  d_in[2];
    const float* degree = (const float*)d_in[3];
    const float* sn_g   = (const float*)d_in[4];
    const float* sn_b   = (const float*)d_in[5];
    const float* nn_g   = (const float*)d_in[6];
    const float* nn_b   = (const float*)d_in[7];
    const float* W1     = (const float*)d_in[8];
    const float* b1     = (const float*)d_in[9];
    const float* W2     = (const float*)d_in[10];
    const float* b2     = (const float*)d_in[11];

    const int E     = in_sizes[1];
    const int nrows = in_sizes[0] / D;   // B*N
    const int N     = in_sizes[3];

    prep_w1<<<32, 256>>>(W1);
    prep_w2<<<16, 256>>>(W2);
    scan_kernel<<<1, 1024>>>(degree, N);
    fill_kernel<<<(E + 255) / 256, 256>>>(esrc, edst, E);
    gather_kernel<<<(N * 32 + 255) / 256, 256>>>(x, degree, N);

    cudaFuncSetAttribute(fused_kernel, cudaFuncAttributeMaxDynamicSharedMemorySize, SMEM_TOTAL);
    fused_kernel<<<(nrows + MTILE - 1) / MTILE, NTHREADS, SMEM_TOTAL>>>(
        x, sn_g, sn_b, nn_g, nn_b, b1, b2, (float*)d_out, nrows);
}

// round 9
// speedup vs baseline: 2.4429x; 1.0327x over previous
#include <cuda_runtime.h>
#include <cuda_bf16.h>
#include <cstdint>
#include <stdint.h>
#include <math.h>

#define D      128
#define TWO_D  256
#define MTILE  64
#define NTHREADS 256
#define MAXN   50000
#define MAXE   800000

// A image: 64 rows x 256 bf16, row stride 528 bytes (conflict-free LDSM)
#define A_STRIDE 528
#define A_IMG    (64 * A_STRIDE)      // 33792
#define SMEM_AHI 0
#define SMEM_ALO A_IMG
#define SMEM_TOTAL (2 * A_IMG)        // 67584 -> 2 CTAs/SM

// ---------------------------------------------------------------------------
// Device globals
// ---------------------------------------------------------------------------
__device__ int   g_base[MAXN + 1];
__device__ int   g_cursor[MAXN];
__device__ int   g_csr[MAXE];
// Pre-computed mma.sync B fragments (per-lane register images), hi/lo terms.
__device__ uint4 g_B1fh[8192];
__device__ uint4 g_B1fl[8192];
__device__ uint4 g_B2fh[4096];
__device__ uint4 g_B2fl[4096];

// ---------------------------------------------------------------------------
// helpers
// ---------------------------------------------------------------------------
__device__ __forceinline__ uint32_t smem_u32(const void* p) {
    uint32_t a;
    asm("{ .reg .u64 t; cvta.to.shared.u64 t, %1; cvt.u32.u64 %0, t; }" : "=r"(a) : "l"(p));
    return a;
}
__device__ __forceinline__ void ldsm4(uint32_t* r, uint32_t addr) {
    asm volatile("ldmatrix.sync.aligned.m8n8.x4.shared.b16 {%0,%1,%2,%3}, [%4];"
                 : "=r"(r[0]), "=r"(r[1]), "=r"(r[2]), "=r"(r[3]) : "r"(addr));
}
__device__ __forceinline__ void mma16816(float* d, const uint32_t* a, uint32_t b0, uint32_t b1) {
    asm volatile("mma.sync.aligned.m16n8k16.row.col.f32.bf16.bf16.f32 "
                 "{%0,%1,%2,%3}, {%4,%5,%6,%7}, {%8,%9}, {%0,%1,%2,%3};"
                 : "+f"(d[0]), "+f"(d[1]), "+f"(d[2]), "+f"(d[3])
                 : "r"(a[0]), "r"(a[1]), "r"(a[2]), "r"(a[3]), "r"(b0), "r"(b1));
}
__device__ __forceinline__ int a_off(int row, int k) {
    return row * A_STRIDE + ((k >> 3) << 4) + ((k & 7) << 1);
}
__device__ __forceinline__ void split_pair(char* hi_base, char* lo_base, int off,
                                           float v0, float v1) {
    __nv_bfloat16 h0 = __float2bfloat16(v0);
    __nv_bfloat16 h1 = __float2bfloat16(v1);
    __nv_bfloat16 l0 = __float2bfloat16(v0 - __bfloat162float(h0));
    __nv_bfloat16 l1 = __float2bfloat16(v1 - __bfloat162float(h1));
    *reinterpret_cast<__nv_bfloat162*>(hi_base + off) = __halves2bfloat162(h0, h1);
    *reinterpret_cast<__nv_bfloat162*>(lo_base + off) = __halves2bfloat162(l0, l1);
}
__device__ __forceinline__ uint32_t pack_hi(float a, float b) {
    __nv_bfloat162 v = __halves2bfloat162(__float2bfloat16(a), __float2bfloat16(b));
    return *reinterpret_cast<uint32_t*>(&v);
}
__device__ __forceinline__ uint32_t pack_lo(float a, float b) {
    __nv_bfloat16 ha = __float2bfloat16(a), hb = __float2bfloat16(b);
    __nv_bfloat162 v = __halves2bfloat162(__float2bfloat16(a - __bfloat162float(ha)),
                                          __float2bfloat16(b - __bfloat162float(hb)));
    return *reinterpret_cast<uint32_t*>(&v);
}

// ---------------------------------------------------------------------------
// Prep: weights -> per-lane mma B fragments (hi/lo split)
// ---------------------------------------------------------------------------
__global__ void prep_w1(const float* __restrict__ W1) {
    int idx = blockIdx.x * blockDim.x + threadIdx.x;
    if (idx >= 8192) return;
    int lane = idx & 31, ng = (idx >> 5) & 15, ks = idx >> 9;
    int n0 = ng * 16 + (lane >> 2);
    int kb = ks * 16 + (lane & 3) * 2;
    float a0 = W1[(size_t)(kb)     * 256 + n0], a1 = W1[(size_t)(kb + 1) * 256 + n0];
    float a2 = W1[(size_t)(kb + 8) * 256 + n0], a3 = W1[(size_t)(kb + 9) * 256 + n0];
    float a4 = W1[(size_t)(kb)     * 256 + n0 + 8], a5 = W1[(size_t)(kb + 1) * 256 + n0 + 8];
    float a6 = W1[(size_t)(kb + 8) * 256 + n0 + 8], a7 = W1[(size_t)(kb + 9) * 256 + n0 + 8];
    g_B1fh[idx] = make_uint4(pack_hi(a0, a1), pack_hi(a2, a3), pack_hi(a4, a5), pack_hi(a6, a7));
    g_B1fl[idx] = make_uint4(pack_lo(a0, a1), pack_lo(a2, a3), pack_lo(a4, a5), pack_lo(a6, a7));
}
__global__ void prep_w2(const float* __restrict__ W2) {
    int idx = blockIdx.x * blockDim.x + threadIdx.x;
    if (idx >= 4096) return;
    int lane = idx & 31, ng = (idx >> 5) & 7, ks = idx >> 8;
    int n0 = ng * 16 + (lane >> 2);
    int kb = ks * 16 + (lane & 3) * 2;
    float a0 = W2[(size_t)(kb)     * 128 + n0], a1 = W2[(size_t)(kb + 1) * 128 + n0];
    float a2 = W2[(size_t)(kb + 8) * 128 + n0], a3 = W2[(size_t)(kb + 9) * 128 + n0];
    float a4 = W2[(size_t)(kb)     * 128 + n0 + 8], a5 = W2[(size_t)(kb + 1) * 128 + n0 + 8];
    float a6 = W2[(size_t)(kb + 8) * 128 + n0 + 8], a7 = W2[(size_t)(kb + 9) * 128 + n0 + 8];
    g_B2fh[idx] = make_uint4(pack_hi(a0, a1), pack_hi(a2, a3), pack_hi(a4, a5), pack_hi(a6, a7));
    g_B2fl[idx] = make_uint4(pack_lo(a0, a1), pack_lo(a2, a3), pack_lo(a4, a5), pack_lo(a6, a7));
}

// ---------------------------------------------------------------------------
// CSR build
// ---------------------------------------------------------------------------
__global__ void scan_kernel(const float* __restrict__ degree, int N) {
    __shared__ int warp_sums[32];
    __shared__ int s_carry;
    const int tid = threadIdx.x, lane = tid & 31, wid = tid >> 5;
    if (tid == 0) s_carry = 0;
    __syncthreads();
    for (int chunk = 0; chunk < N; chunk += 1024) {
        int i = chunk + tid;
        int v = (i < N) ? (int)degree[i] : 0;
        int inc = v;
#pragma unroll
        for (int o = 1; o < 32; o <<= 1) {
            int t = __shfl_up_sync(0xffffffffu, inc, o);
            if (lane >= o) inc += t;
        }
        if (lane == 31) warp_sums[wid] = inc;
        __syncthreads();
        if (wid == 0) {
            int ws = warp_sums[lane];
#pragma unroll
            for (int o = 1; o < 32; o <<= 1) {
                int t = __shfl_up_sync(0xffffffffu, ws, o);
                if (lane >= o) ws += t;
            }
            warp_sums[lane] = ws;
        }
        __syncthreads();
        int warp_prefix = (wid > 0) ? warp_sums[wid - 1] : 0;
        int excl = s_carry + warp_prefix + inc - v;
        if (i < N) { g_base[i] = excl; g_cursor[i] = 0; }
        __syncthreads();
        if (tid == 1023) s_carry += warp_sums[31];
        __syncthreads();
    }
    if (tid == 0) g_base[N] = s_carry;
}

__global__ void fill_kernel(const int* __restrict__ esrc,
                            const int* __restrict__ edst, int E) {
    int e = blockIdx.x * blockDim.x + threadIdx.x;
    if (e >= E) return;
    int t = edst[e];
    int pos = g_base[t] + atomicAdd(&g_cursor[t], 1);
    if (pos < MAXE) g_csr[pos] = esrc[e];
}

// ---------------------------------------------------------------------------
// Fused kernel: CSR-gather + LN(x) + LN(neighbor) -> split-bf16 mma GEMM1
//               -> GELU -> GEMM2 -> bias + residual.  2 CTAs/SM, no g_neighbor.
// ---------------------------------------------------------------------------
__global__ void __launch_bounds__(NTHREADS, 2)
fused_kernel(const float* __restrict__ x,
             const float* __restrict__ degree,
             const float* __restrict__ sn_g, const float* __restrict__ sn_b,
             const float* __restrict__ nn_g, const float* __restrict__ nn_b,
             const float* __restrict__ b1,  const float* __restrict__ b2,
             float* __restrict__ out, int N, int nrows) {
    extern __shared__ char sm[];
    const uint32_t smem_base = smem_u32(sm);
    char* Ahi = sm + SMEM_AHI;
    char* Alo = sm + SMEM_ALO;

    const int tid  = threadIdx.x;
    const int lane = tid & 31;
    const int warp = tid >> 5;
    const int wm   = warp & 1;
    const int wn   = warp >> 1;
    const int row0 = blockIdx.x * MTILE;
    const int g    = lane >> 3;
    const int lr   = lane & 7;

    // ---------------- Stage 1: gather + LayerNorms -> A images --------------
    {
        const float4 g1  = *reinterpret_cast<const float4*>(sn_g + lane * 4);
        const float4 be1 = *reinterpret_cast<const float4*>(sn_b + lane * 4);
        const float4 g2  = *reinterpret_cast<const float4*>(nn_g + lane * 4);
        const float4 be2 = *reinterpret_cast<const float4*>(nn_b + lane * 4);
        const int k0 = lane * 4;
#pragma unroll
        for (int rr = 0; rr < 8; rr++) {
            const int r    = warp * 8 + rr;
            const int grow = row0 + r;
            if (grow < nrows) {
                // ---- LN(x) ----
                float4 xv = *reinterpret_cast<const float4*>(x + (size_t)grow * D + k0);
                float sum  = xv.x + xv.y + xv.z + xv.w;
                float sumq = xv.x * xv.x + xv.y * xv.y + xv.z * xv.z + xv.w * xv.w;
#pragma unroll
                for (int o = 16; o > 0; o >>= 1) {
                    sum  += __shfl_xor_sync(0xffffffffu, sum, o);
                    sumq += __shfl_xor_sync(0xffffffffu, sumq, o);
                }
                float mn   = sum * (1.0f / 128.0f);
                float rstd = rsqrtf(sumq * (1.0f / 128.0f) - mn * mn + 1e-5f);
                split_pair(Ahi, Alo, a_off(r, k0),     (xv.x - mn) * rstd * g1.x + be1.x,
                                                       (xv.y - mn) * rstd * g1.y + be1.y);
                split_pair(Ahi, Alo, a_off(r, k0 + 2), (xv.z - mn) * rstd * g1.z + be1.z,
                                                       (xv.w - mn) * rstd * g1.w + be1.w);

                // ---- CSR gather of neighbors (this row's node, this batch) --
                int node = grow, boff = 0;
                if (grow >= N) { node = grow - N; boff = N; }
                const float dgf = degree[node];
                const int   deg = (int)dgf;
                const float inv = 1.0f / fmaxf(dgf, 1.0f);
                const int   bs  = g_base[node];
                float4 nv = make_float4(0.f, 0.f, 0.f, 0.f);
                int j = 0;
                for (; j + 2 <= deg; j += 2) {
                    int s0 = g_csr[bs + j], s1 = g_csr[bs + j + 1];
                    const float4 v0 = *reinterpret_cast<const float4*>(
                        x + ((size_t)(boff + s0)) * D + k0);
                    const float4 v1 = *reinterpret_cast<const float4*>(
                        x + ((size_t)(boff + s1)) * D + k0);
                    nv.x += v0.x + v1.x; nv.y += v0.y + v1.y;
                    nv.z += v0.z + v1.z; nv.w += v0.w + v1.w;
                }
                if (j < deg) {
                    int s0 = g_csr[bs + j];
                    const float4 v0 = *reinterpret_cast<const float4*>(
                        x + ((size_t)(boff + s0)) * D + k0);
                    nv.x += v0.x; nv.y += v0.y; nv.z += v0.z; nv.w += v0.w;
                }
                nv.x *= inv; nv.y *= inv; nv.z *= inv; nv.w *= inv;

                // ---- LN(neighbor) ----
                sum  = nv.x + nv.y + nv.z + nv.w;
                sumq = nv.x * nv.x + nv.y * nv.y + nv.z * nv.z + nv.w * nv.w;
#pragma unroll
                for (int o = 16; o > 0; o >>= 1) {
                    sum  += __shfl_xor_sync(0xffffffffu, sum, o);
                    sumq += __shfl_xor_sync(0xffffffffu, sumq, o);
                }
                mn   = sum * (1.0f / 128.0f);
                rstd = rsqrtf(sumq * (1.0f / 128.0f) - mn * mn + 1e-5f);
                split_pair(Ahi, Alo, a_off(r, 128 + k0),     (nv.x - mn) * rstd * g2.x + be2.x,
                                                             (nv.y - mn) * rstd * g2.y + be2.y);
                split_pair(Ahi, Alo, a_off(r, 128 + k0 + 2), (nv.z - mn) * rstd * g2.z + be2.z,
                                                             (nv.w - mn) * rstd * g2.w + be2.w);
            } else {
                split_pair(Ahi, Alo, a_off(r, k0),           0.f, 0.f);
                split_pair(Ahi, Alo, a_off(r, k0 + 2),       0.f, 0.f);
                split_pair(Ahi, Alo, a_off(r, 128 + k0),     0.f, 0.f);
                split_pair(Ahi, Alo, a_off(r, 128 + k0 + 2), 0.f, 0.f);
            }
        }
    }
    __syncthreads();

    // ---------------- Stage 2: GEMM1 (64 x 256 x 256, 3 split terms) --------
    float acc[2][8][4];
#pragma unroll
    for (int i = 0; i < 2; i++)
#pragma unroll
        for (int j = 0; j < 8; j++)
#pragma unroll
            for (int r = 0; r < 4; r++) acc[i][j][r] = 0.f;

#pragma unroll 2
    for (int ks = 0; ks < 16; ks++) {
        const int kabs = ks * 16;
        uint32_t ahi[2][4], alo[2][4];
#pragma unroll
        for (int ti = 0; ti < 2; ti++) {
            int row = wm * 32 + ti * 16 + (g & 1) * 8 + lr;
            uint32_t off = row * A_STRIDE + (((kabs >> 3) + (g >> 1)) << 4);
            ldsm4(ahi[ti], smem_base + SMEM_AHI + off);
            ldsm4(alo[ti], smem_base + SMEM_ALO + off);
        }
#pragma unroll
        for (int jj = 0; jj < 4; jj++) {
            const int fi = (ks * 16 + wn * 4 + jj) * 32 + lane;
            const uint4 fh = g_B1fh[fi];
            const uint4 fl = g_B1fl[fi];
#pragma unroll
            for (int ti = 0; ti < 2; ti++) {
                mma16816(acc[ti][2 * jj],     ahi[ti], fh.x, fh.y);
                mma16816(acc[ti][2 * jj],     ahi[ti], fl.x, fl.y);
                mma16816(acc[ti][2 * jj],     alo[ti], fh.x, fh.y);
                mma16816(acc[ti][2 * jj + 1], ahi[ti], fh.z, fh.w);
                mma16816(acc[ti][2 * jj + 1], ahi[ti], fl.z, fl.w);
                mma16816(acc[ti][2 * jj + 1], alo[ti], fh.z, fh.w);
            }
        }
    }

    // ---------------- Stage 3: bias + GELU -> A2 images ---------------------
    __syncthreads();
#pragma unroll
    for (int tj = 0; tj < 8; tj++) {
        const int col = wn * 64 + tj * 8 + (lane & 3) * 2;
        const float2 bb = *reinterpret_cast<const float2*>(b1 + col);
#pragma unroll
        for (int ti = 0; ti < 2; ti++)
#pragma unroll
            for (int rp = 0; rp < 2; rp++) {
                int row = wm * 32 + ti * 16 + (lane >> 2) + rp * 8;
                float v0 = acc[ti][tj][rp * 2 + 0] + bb.x;
                float v1 = acc[ti][tj][rp * 2 + 1] + bb.y;
                v0 = 0.5f * v0 * (1.0f + erff(v0 * 0.70710678118654752f));
                v1 = 0.5f * v1 * (1.0f + erff(v1 * 0.70710678118654752f));
                split_pair(Ahi, Alo, a_off(row, col), v0, v1);
            }
    }
    __syncthreads();

    // ---------------- Stage 4: GEMM2 (64 x 128 x 256, 3 split terms) --------
    float c2[2][4][4];
#pragma unroll
    for (int i = 0; i < 2; i++)
#pragma unroll
        for (int j = 0; j < 4; j++)
#pragma unroll
            for (int r = 0; r < 4; r++) c2[i][j][r] = 0.f;

#pragma unroll 2
    for (int ks = 0; ks < 16; ks++) {
        const int kabs = ks * 16;
        uint32_t ahi[2][4], alo[2][4];
#pragma unroll
        for (int ti = 0; ti < 2; ti++) {
            int row = wm * 32 + ti * 16 + (g & 1) * 8 + lr;
            uint32_t off = row * A_STRIDE + (((kabs >> 3) + (g >> 1)) << 4);
            ldsm4(ahi[ti], smem_base + SMEM_AHI + off);
            ldsm4(alo[ti], smem_base + SMEM_ALO + off);
        }
#pragma unroll
        for (int jj = 0; jj < 2; jj++) {
            const int fi = (ks * 8 + wn * 2 + jj) * 32 + lane;
            const uint4 fh = g_B2fh[fi];
            const uint4 fl = g_B2fl[fi];
#pragma unroll
            for (int ti = 0; ti < 2; ti++) {
                mma16816(c2[ti][2 * jj],     ahi[ti], fh.x, fh.y);
                mma16816(c2[ti][2 * jj],     ahi[ti], fl.x, fl.y);
                mma16816(c2[ti][2 * jj],     alo[ti], fh.x, fh.y);
                mma16816(c2[ti][2 * jj + 1], ahi[ti], fh.z, fh.w);
                mma16816(c2[ti][2 * jj + 1], ahi[ti], fl.z, fl.w);
                mma16816(c2[ti][2 * jj + 1], alo[ti], fh.z, fh.w);
            }
        }
    }

    // ---------------- Stage 5: bias + residual + store ----------------------
#pragma unroll
    for (int tj = 0; tj < 4; tj++) {
        const int col = wn * 32 + tj * 8 + (lane & 3) * 2;
        const float2 bb = *reinterpret_cast<const float2*>(b2 + col);
#pragma unroll
        for (int ti = 0; ti < 2; ti++)
#pragma unroll
            for (int rp = 0; rp < 2; rp++) {
                int row  = wm * 32 + ti * 16 + (lane >> 2) + rp * 8;
                int grow = row0 + row;
                if (grow < nrows) {
                    const float2 xv = *reinterpret_cast<const float2*>(x + (size_t)grow * D + col);
                    float2 o;
                    o.x = xv.x + c2[ti][tj][rp * 2 + 0] + bb.x;
                    o.y = xv.y + c2[ti][tj][rp * 2 + 1] + bb.y;
                    *reinterpret_cast<float2*>(out + (size_t)grow * D + col) = o;
                }
            }
    }
}

// ---------------------------------------------------------------------------
extern "C" void kernel_launch(void* const* d_in, const int* in_sizes, int n_in,
                              void* d_out, int out_size) {
    const float* x      = (const float*)d_in[0];
    const int*   esrc   = (const int*)  d_in[1];
    const int*   edst   = (const int*)  d_in[2];
    const float* degree = (const float*)d_in[3];
    const float* sn_g   = (const float*)d_in[4];
    const float* sn_b   = (const float*)d_in[5];
    const float* nn_g   = (const float*)d_in[6];
    const float* nn_b   = (const float*)d_in[7];
    const float* W1     = (const float*)d_in[8];
    const float* b1     = (const float*)d_in[9];
    const float* W2     = (const float*)d_in[10];
    const float* b2     = (const float*)d_in[11];

    const int E     = in_sizes[1];
    const int nrows = in_sizes[0] / D;   // B*N
    const int N     = in_sizes[3];

    prep_w1<<<32, 256>>>(W1);
    prep_w2<<<16, 256>>>(W2);
    scan_kernel<<<1, 1024>>>(degree, N);
    fill_kernel<<<(E + 255) / 256, 256>>>(esrc, edst, E);

    cudaFuncSetAttribute(fused_kernel, cudaFuncAttributeMaxDynamicSharedMemorySize, SMEM_TOTAL);
    fused_kernel<<<(nrows + MTILE - 1) / MTILE, NTHREADS, SMEM_TOTAL>>>(
        x, degree, sn_g, sn_b, nn_g, nn_b, b1, b2, (float*)d_out, N, nrows);
}